// round 1
// baseline (speedup 1.0000x reference)
#include <cuda_runtime.h>

#define BB 8
#define SS 1024
#define DD 512
#define NHEADS 8
#define DHEAD 64
#define MROWS (BB*SS)   // 8192

// Scratch (no allocation allowed): Q, K_eff, V, H in [B,S,D] row-major
__device__ float gQ[MROWS*DD];
__device__ float gK[MROWS*DD];
__device__ float gV[MROWS*DD];
__device__ float gH[MROWS*DD];

// ---------------------------------------------------------------------------
// Kernel 1: Y = xs2 @ W1 + xt @ W2   (z selects q/k/v weights & output)
// For z==1 (K), fold WK bias: K[b,s,h*64+dh] += WK[dh, s]
// 64x64 tile, 16x16 threads, 4x4 per thread, K-tile 16, two input phases.
// ---------------------------------------------------------------------------
__global__ void qkv_gemm(const float* __restrict__ xs, const float* __restrict__ xt,
                         const float* __restrict__ Wqs, const float* __restrict__ Wks,
                         const float* __restrict__ Wvs, const float* __restrict__ Wqt,
                         const float* __restrict__ Wkt, const float* __restrict__ Wvt,
                         const float* __restrict__ WKb)
{
    __shared__ float As[16*68];   // transposed A tile, padded
    __shared__ float Bs[16*64];

    const int z = blockIdx.z;
    const float* W1 = (z==0) ? Wqs : ((z==1) ? Wks : Wvs);
    const float* W2 = (z==0) ? Wqt : ((z==1) ? Wkt : Wvt);
    float* C = (z==0) ? gQ : ((z==1) ? gK : gV);

    const int rowBase = blockIdx.y * 64;
    const int colBase = blockIdx.x * 64;
    const int tx = threadIdx.x, ty = threadIdx.y;
    const int t = ty * 16 + tx;

    const int la_row = t >> 2;          // 0..63
    const int la_k   = (t & 3) * 4;     // 0,4,8,12
    const int lb_k   = t >> 4;          // 0..15
    const int lb_c   = (t & 15) * 4;    // 0..60

    float acc[4][4];
#pragma unroll
    for (int i = 0; i < 4; i++)
#pragma unroll
        for (int j = 0; j < 4; j++) acc[i][j] = 0.f;

#pragma unroll
    for (int phase = 0; phase < 2; phase++) {
        const float* A = phase ? xt : xs;   // xs raw-reshaped is contiguous [8192,512]
        const float* W = phase ? W2 : W1;
        for (int k0 = 0; k0 < DD; k0 += 16) {
            float4 av = *(const float4*)&A[(rowBase + la_row) * DD + k0 + la_k];
            float4 bv = *(const float4*)&W[(k0 + lb_k) * DD + colBase + lb_c];
            __syncthreads();
            As[(la_k+0)*68 + la_row] = av.x;
            As[(la_k+1)*68 + la_row] = av.y;
            As[(la_k+2)*68 + la_row] = av.z;
            As[(la_k+3)*68 + la_row] = av.w;
            *(float4*)&Bs[lb_k*64 + lb_c] = bv;
            __syncthreads();
#pragma unroll
            for (int kk = 0; kk < 16; kk++) {
                float4 a = *(const float4*)&As[kk*68 + ty*4];
                float4 b = *(const float4*)&Bs[kk*64 + tx*4];
                float ar[4] = {a.x, a.y, a.z, a.w};
                float br[4] = {b.x, b.y, b.z, b.w};
#pragma unroll
                for (int i = 0; i < 4; i++)
#pragma unroll
                    for (int j = 0; j < 4; j++)
                        acc[i][j] += ar[i] * br[j];
            }
        }
    }

#pragma unroll
    for (int i = 0; i < 4; i++) {
        int r = rowBase + ty*4 + i;
        int s = r & (SS - 1);
        float4 v;
        float* vp = (float*)&v;
#pragma unroll
        for (int j = 0; j < 4; j++) {
            int c = colBase + tx*4 + j;
            float val = acc[i][j];
            if (z == 1) val += WKb[(c & (DHEAD-1)) * SS + s];
            vp[j] = val;
        }
        *(float4*)&C[r*DD + colBase + tx*4] = v;
    }
}

// ---------------------------------------------------------------------------
// Kernel 2: causal flash attention per (b,h,qtile). BM=64, key tiles of 64.
// 256 threads (8 warps x 8 rows). Bias already folded into gK.
// ---------------------------------------------------------------------------
__global__ void attn_kernel()
{
    extern __shared__ float sm[];
    float* Qs = sm;                 // 64*64
    float* Ks = Qs + 64*64;         // 64*65
    float* Vs = Ks + 64*65;         // 64*65
    float* Pb = Vs + 64*65;         // 64*64 (8 warps * 8 rows * 64)

    const int bh = blockIdx.x;              // 0..63
    const int qt = blockIdx.y;              // 0..15
    const int b = bh >> 3, h = bh & 7;
    const int t = threadIdx.x;
    const int warp = t >> 5, lane = t & 31;

    const float* Qg = gQ + (size_t)b * SS * DD + h * DHEAD;
    const float* Kg = gK + (size_t)b * SS * DD + h * DHEAD;
    const float* Vg = gV + (size_t)b * SS * DD + h * DHEAD;

    // load Q tile (pre-scaled by 1/sqrt(dh))
    for (int idx = t; idx < 64*16; idx += 256) {
        int r = idx >> 4, c = (idx & 15) * 4;
        float4 q4 = *(const float4*)&Qg[(qt*64 + r) * DD + c];
        Qs[r*64 + c+0] = q4.x * 0.125f;
        Qs[r*64 + c+1] = q4.y * 0.125f;
        Qs[r*64 + c+2] = q4.z * 0.125f;
        Qs[r*64 + c+3] = q4.w * 0.125f;
    }

    float o0[8], o1[8], m[8], l[8];
#pragma unroll
    for (int r = 0; r < 8; r++) { o0[r]=0.f; o1[r]=0.f; m[r]=-1e30f; l[r]=0.f; }

    for (int kt = 0; kt <= qt; kt++) {
        __syncthreads();
        for (int idx = t; idx < 64*16; idx += 256) {
            int r = idx >> 4, c = (idx & 15) * 4;
            float4 k4 = *(const float4*)&Kg[(kt*64 + r) * DD + c];
            float4 v4 = *(const float4*)&Vg[(kt*64 + r) * DD + c];
            Ks[r*65 + c+0] = k4.x; Ks[r*65 + c+1] = k4.y;
            Ks[r*65 + c+2] = k4.z; Ks[r*65 + c+3] = k4.w;
            Vs[r*65 + c+0] = v4.x; Vs[r*65 + c+1] = v4.y;
            Vs[r*65 + c+2] = v4.z; Vs[r*65 + c+3] = v4.w;
        }
        __syncthreads();

        // scores: 8 rows per warp, lane owns key cols (lane, lane+32)
        float s0[8], s1[8];
#pragma unroll
        for (int r = 0; r < 8; r++) { s0[r]=0.f; s1[r]=0.f; }
#pragma unroll 8
        for (int kk = 0; kk < 64; kk++) {
            float k0 = Ks[lane*65 + kk];
            float k1 = Ks[(lane+32)*65 + kk];
#pragma unroll
            for (int r = 0; r < 8; r++) {
                float qv = Qs[(warp*8 + r)*64 + kk];
                s0[r] += qv * k0;
                s1[r] += qv * k1;
            }
        }

        if (kt == qt) {
#pragma unroll
            for (int r = 0; r < 8; r++) {
                int qi = warp*8 + r;
                if (lane      > qi) s0[r] = -1e30f;
                if (lane + 32 > qi) s1[r] = -1e30f;
            }
        }

        // online softmax update per row
#pragma unroll
        for (int r = 0; r < 8; r++) {
            float mx = fmaxf(s0[r], s1[r]);
#pragma unroll
            for (int off = 16; off; off >>= 1)
                mx = fmaxf(mx, __shfl_xor_sync(0xffffffffu, mx, off));
            float mnew = fmaxf(m[r], mx);
            float alpha = __expf(m[r] - mnew);
            float p0 = __expf(s0[r] - mnew);
            float p1 = __expf(s1[r] - mnew);
            float ps = p0 + p1;
#pragma unroll
            for (int off = 16; off; off >>= 1)
                ps += __shfl_xor_sync(0xffffffffu, ps, off);
            l[r] = l[r] * alpha + ps;
            o0[r] *= alpha; o1[r] *= alpha;
            m[r] = mnew;
            Pb[(warp*8 + r)*64 + lane]      = p0;
            Pb[(warp*8 + r)*64 + lane + 32] = p1;
        }
        __syncwarp();

        // O += P @ V  (lane owns dims lane, lane+32)
#pragma unroll 8
        for (int j = 0; j < 64; j++) {
            float v0 = Vs[j*65 + lane];
            float v1 = Vs[j*65 + lane + 32];
#pragma unroll
            for (int r = 0; r < 8; r++) {
                float pj = Pb[(warp*8 + r)*64 + j];
                o0[r] += pj * v0;
                o1[r] += pj * v1;
            }
        }
    }

    float* Hg = gH + (size_t)b * SS * DD + h * DHEAD;
#pragma unroll
    for (int r = 0; r < 8; r++) {
        int row = warp*8 + r;
        float inv = 1.f / l[r];
        Hg[(qt*64 + row) * DD + lane]      = o0[r] * inv;
        Hg[(qt*64 + row) * DD + lane + 32] = o1[r] * inv;
    }
}

// ---------------------------------------------------------------------------
// Kernel 3: out = H @ Wo  -> d_out (raw [B,S,D] layout == [B,D,IMG,IMG] view)
// ---------------------------------------------------------------------------
__global__ void out_gemm(const float* __restrict__ Wo, float* __restrict__ out)
{
    __shared__ float As[16*68];
    __shared__ float Bs[16*64];

    const int rowBase = blockIdx.y * 64;
    const int colBase = blockIdx.x * 64;
    const int tx = threadIdx.x, ty = threadIdx.y;
    const int t = ty * 16 + tx;

    const int la_row = t >> 2;
    const int la_k   = (t & 3) * 4;
    const int lb_k   = t >> 4;
    const int lb_c   = (t & 15) * 4;

    float acc[4][4];
#pragma unroll
    for (int i = 0; i < 4; i++)
#pragma unroll
        for (int j = 0; j < 4; j++) acc[i][j] = 0.f;

    for (int k0 = 0; k0 < DD; k0 += 16) {
        float4 av = *(const float4*)&gH[(rowBase + la_row) * DD + k0 + la_k];
        float4 bv = *(const float4*)&Wo[(k0 + lb_k) * DD + colBase + lb_c];
        __syncthreads();
        As[(la_k+0)*68 + la_row] = av.x;
        As[(la_k+1)*68 + la_row] = av.y;
        As[(la_k+2)*68 + la_row] = av.z;
        As[(la_k+3)*68 + la_row] = av.w;
        *(float4*)&Bs[lb_k*64 + lb_c] = bv;
        __syncthreads();
#pragma unroll
        for (int kk = 0; kk < 16; kk++) {
            float4 a = *(const float4*)&As[kk*68 + ty*4];
            float4 b = *(const float4*)&Bs[kk*64 + tx*4];
            float ar[4] = {a.x, a.y, a.z, a.w};
            float br[4] = {b.x, b.y, b.z, b.w};
#pragma unroll
            for (int i = 0; i < 4; i++)
#pragma unroll
                for (int j = 0; j < 4; j++)
                    acc[i][j] += ar[i] * br[j];
        }
    }

#pragma unroll
    for (int i = 0; i < 4; i++) {
        int r = rowBase + ty*4 + i;
        float4 v;
        v.x = acc[i][0]; v.y = acc[i][1]; v.z = acc[i][2]; v.w = acc[i][3];
        *(float4*)&out[r*DD + colBase + tx*4] = v;
    }
}

// ---------------------------------------------------------------------------
extern "C" void kernel_launch(void* const* d_in, const int* in_sizes, int n_in,
                              void* d_out, int out_size)
{
    const float* xs  = (const float*)d_in[0];
    const float* xt  = (const float*)d_in[1];
    const float* Wqs = (const float*)d_in[2];
    const float* Wks = (const float*)d_in[3];
    const float* Wvs = (const float*)d_in[4];
    const float* Wqt = (const float*)d_in[5];
    const float* Wkt = (const float*)d_in[6];
    const float* Wvt = (const float*)d_in[7];
    const float* WKb = (const float*)d_in[8];
    const float* Wo  = (const float*)d_in[9];
    float* out = (float*)d_out;

    const int attn_smem = (64*64 + 64*65 + 64*65 + 64*64) * (int)sizeof(float); // 66048
    cudaFuncSetAttribute(attn_kernel, cudaFuncAttributeMaxDynamicSharedMemorySize, attn_smem);

    dim3 gblk(16, 16);
    qkv_gemm<<<dim3(DD/64, MROWS/64, 3), gblk>>>(xs, xt, Wqs, Wks, Wvs, Wqt, Wkt, Wvt, WKb);
    attn_kernel<<<dim3(BB*NHEADS, SS/64), 256, attn_smem>>>();
    out_gemm<<<dim3(DD/64, MROWS/64), gblk>>>(Wo, out);
}

// round 3
// speedup vs baseline: 1.7004x; 1.7004x over previous
#include <cuda_runtime.h>
#include <cuda_bf16.h>
#include <cstdint>

#define BB 8
#define SS 1024
#define DD 512
#define NHEADS 8
#define DHEAD 64
#define MROWS (BB*SS)   // 8192

// ---------------- scratch (no allocation allowed) ----------------
__device__ float gC[(size_t)3*MROWS*DD];                 // Q, K_eff, V (fp32)
__device__ __nv_bfloat16 gA[(size_t)MROWS*2048];         // [xs_h | xt_h | xs_l | xt_l]
__device__ __nv_bfloat16 gHs[(size_t)MROWS*1024];        // [H_h | H_l]
__device__ __nv_bfloat16 gBt[(size_t)3*512*3072];        // per-z W_big^T  [n][k]
__device__ __nv_bfloat16 gWoT[(size_t)512*1536];         // Wo_big^T [n][k]

// ---------------- warp-mma helpers (sm_80+ ISA, works on plain sm_103) ------
__device__ __forceinline__ void ldsm4(uint32_t* r, uint32_t addr)
{
    asm volatile("ldmatrix.sync.aligned.m8n8.x4.shared.b16 {%0,%1,%2,%3}, [%4];"
        : "=r"(r[0]), "=r"(r[1]), "=r"(r[2]), "=r"(r[3]) : "r"(addr));
}

__device__ __forceinline__ void mma16816(float* c, const uint32_t* a, const uint32_t* b)
{
    asm volatile(
        "mma.sync.aligned.m16n8k16.row.col.f32.bf16.bf16.f32 "
        "{%0,%1,%2,%3}, {%4,%5,%6,%7}, {%8,%9}, {%0,%1,%2,%3};"
        : "+f"(c[0]), "+f"(c[1]), "+f"(c[2]), "+f"(c[3])
        : "r"(a[0]), "r"(a[1]), "r"(a[2]), "r"(a[3]), "r"(b[0]), "r"(b[1]));
}

// ---------------------------------------------------------------------------
// prep kernels: bf16 hi/lo splits
// ---------------------------------------------------------------------------
__global__ void prep_A(const float* __restrict__ xs, const float* __restrict__ xt)
{
    int r = blockIdx.x;
    int c = threadIdx.x;            // 512 threads
    float a = xs[(size_t)r*DD + c];
    float b = xt[(size_t)r*DD + c];
    __nv_bfloat16 ah = __float2bfloat16(a);
    __nv_bfloat16 bh = __float2bfloat16(b);
    __nv_bfloat16* row = gA + (size_t)r*2048;
    row[c]        = ah;
    row[512 + c]  = bh;
    row[1024 + c] = __float2bfloat16(a - __bfloat162float(ah));
    row[1536 + c] = __float2bfloat16(b - __bfloat162float(bh));
}

// gBt[z][n][k]: k 512-blocks 0..5 -> W1h, W2h, W1h, W2h, W1l, W2l
__global__ void prep_W(const float* __restrict__ Wqs, const float* __restrict__ Wks,
                       const float* __restrict__ Wvs, const float* __restrict__ Wqt,
                       const float* __restrict__ Wkt, const float* __restrict__ Wvt)
{
    int idx = blockIdx.x * 256 + threadIdx.x;   // 3*512*3072 total
    int z   = idx / (512*3072);
    int rem = idx % (512*3072);
    int n   = rem / 3072;
    int k   = rem % 3072;
    const float* W1 = (z==0) ? Wqs : ((z==1) ? Wks : Wvs);
    const float* W2 = (z==0) ? Wqt : ((z==1) ? Wkt : Wvt);
    int kh = k >> 9, ks = k & 511;
    const float* M = (kh & 1) ? W2 : W1;
    float x = M[(size_t)ks*DD + n];
    __nv_bfloat16 v;
    if (kh < 4) v = __float2bfloat16(x);
    else {
        __nv_bfloat16 h = __float2bfloat16(x);
        v = __float2bfloat16(x - __bfloat162float(h));
    }
    gBt[idx] = v;
}

// gWoT[n][k]: k 512-blocks 0..2 -> Wo_h, Wo_h, Wo_l
__global__ void prep_Wo(const float* __restrict__ Wo)
{
    int idx = blockIdx.x * 256 + threadIdx.x;   // 512*1536 total
    int n = idx / 1536;
    int k = idx % 1536;
    int kh = k >> 9, ks = k & 511;
    float x = Wo[(size_t)ks*DD + n];
    __nv_bfloat16 v;
    if (kh < 2) v = __float2bfloat16(x);
    else {
        __nv_bfloat16 h = __float2bfloat16(x);
        v = __float2bfloat16(x - __bfloat162float(h));
    }
    gWoT[idx] = v;
}

// ---------------------------------------------------------------------------
// bf16 mma.sync GEMM: C[M,512] = A[M,Keff] @ B[Keff,512]
// block tile 128x128, warp tile 64x32 (2x4 warps), BK=64, cp.async 2-stage.
// mode 0: QKV  (A=gA w2048, remap 32, Bt=gBt[z], 48 chunks, C=gC[z], bias z==1)
// mode 1: OUT  (A=gHs w1024, remap 16, Bt=gWoT, 24 chunks, C=outp)
// ---------------------------------------------------------------------------
#define SROW 72   // padded smem row (bf16 elems): 144B, conflict-free ldmatrix

__global__ __launch_bounds__(256)
void mma_gemm(int mode, float* __restrict__ outp, const float* __restrict__ WKb)
{
    extern __shared__ __nv_bfloat16 sm[];
    __nv_bfloat16* sA = sm;                    // [2][128][SROW]
    __nv_bfloat16* sB = sm + 2*128*SROW;       // [2][128][SROW]

    const __nv_bfloat16* A;
    const __nv_bfloat16* Bt;
    float* C;
    const float* bias = nullptr;
    int aW, remapC, kEff, nChunks;
    const int z = blockIdx.z;
    if (mode == 0) {
        A = gA; aW = 2048; remapC = 32; kEff = 3072; nChunks = 48;
        Bt = gBt + (size_t)z * 512 * 3072;
        C  = gC  + (size_t)z * MROWS * DD;
        if (z == 1) bias = WKb;
    } else {
        A = gHs; aW = 1024; remapC = 16; kEff = 1536; nChunks = 24;
        Bt = gWoT;
        C  = outp;
    }

    const int mBase = blockIdx.y * 128;
    const int nBase = blockIdx.x * 128;
    const int t    = threadIdx.x;
    const int warp = t >> 5;
    const int lane = t & 31;
    const int wm   = warp >> 2;        // 0..1  (M)
    const int wn   = warp & 3;         // 0..3  (N)

    const uint32_t sAu = (uint32_t)__cvta_generic_to_shared(sA);
    const uint32_t sBu = (uint32_t)__cvta_generic_to_shared(sB);

    // cp.async source/dst precompute: 4 A-rows + 4 B-rows per thread
    const int ldRow = t >> 3;          // 0..31 base row
    const int ldSeg = t & 7;           // 16B segment

    float acc[4][4][4];
#pragma unroll
    for (int i = 0; i < 4; i++)
#pragma unroll
        for (int j = 0; j < 4; j++)
#pragma unroll
            for (int q = 0; q < 4; q++) acc[i][j][q] = 0.f;

#define LOAD_CHUNK(cc, buf) do { \
    int acol_ = (((cc) < remapC) ? (cc) : ((cc) - remapC)) << 6; \
    const __nv_bfloat16* Ag_ = A + (size_t)(mBase + ldRow) * aW + acol_ + ldSeg * 8; \
    const __nv_bfloat16* Bg_ = Bt + (size_t)(nBase + ldRow) * kEff + (size_t)(cc) * 64 + ldSeg * 8; \
    uint32_t da_ = sAu + ((buf)*128*SROW + ldRow*SROW + ldSeg*8) * 2; \
    uint32_t db_ = sBu + ((buf)*128*SROW + ldRow*SROW + ldSeg*8) * 2; \
    _Pragma("unroll") \
    for (int rr_ = 0; rr_ < 4; rr_++) { \
        asm volatile("cp.async.cg.shared.global [%0], [%1], 16;" \
            :: "r"(da_ + rr_*32*SROW*2), "l"(__cvta_generic_to_global((const void*)(Ag_ + (size_t)rr_*32*aW)))); \
        asm volatile("cp.async.cg.shared.global [%0], [%1], 16;" \
            :: "r"(db_ + rr_*32*SROW*2), "l"(__cvta_generic_to_global((const void*)(Bg_ + (size_t)rr_*32*kEff)))); \
    } \
    asm volatile("cp.async.commit_group;" ::: "memory"); \
} while (0)

    LOAD_CHUNK(0, 0);

    // ldmatrix per-thread offsets (element units within a [128][SROW] buffer)
    const int aRowL = wm*64 + (lane & 15);          // + mf*16
    const int aColL = (lane >> 4) << 3;             // + ks*16
    const int bRowL = wn*32 + ((lane >> 4) << 3) + (lane & 7);  // + nfp*16
    const int bColL = ((lane >> 3) & 1) << 3;       // + ks*16

    for (int c = 0; c < nChunks; c++) {
        const int buf = c & 1;
        if (c + 1 < nChunks) LOAD_CHUNK(c + 1, buf ^ 1);
        if (c + 1 < nChunks) { asm volatile("cp.async.wait_group 1;" ::: "memory"); }
        else                 { asm volatile("cp.async.wait_group 0;" ::: "memory"); }
        __syncthreads();

        const uint32_t aB = sAu + (buf*128*SROW) * 2;
        const uint32_t bB = sBu + (buf*128*SROW) * 2;
#pragma unroll
        for (int ks = 0; ks < 4; ks++) {
            uint32_t afr[4][4];
#pragma unroll
            for (int mf = 0; mf < 4; mf++)
                ldsm4(afr[mf], aB + (((aRowL + mf*16) * SROW) + ks*16 + aColL) * 2);
            uint32_t bfr[4][2];
#pragma unroll
            for (int nfp = 0; nfp < 2; nfp++) {
                uint32_t r4[4];
                ldsm4(r4, bB + (((bRowL + nfp*16) * SROW) + ks*16 + bColL) * 2);
                bfr[nfp*2+0][0] = r4[0]; bfr[nfp*2+0][1] = r4[1];
                bfr[nfp*2+1][0] = r4[2]; bfr[nfp*2+1][1] = r4[3];
            }
#pragma unroll
            for (int mf = 0; mf < 4; mf++)
#pragma unroll
                for (int nf = 0; nf < 4; nf++)
                    mma16816(acc[mf][nf], afr[mf], bfr[nf]);
        }
        __syncthreads();
    }

    // epilogue
    const int g   = lane >> 2;
    const int tig = lane & 3;
#pragma unroll
    for (int mf = 0; mf < 4; mf++) {
        int row0 = mBase + wm*64 + mf*16 + g;
#pragma unroll
        for (int nf = 0; nf < 4; nf++) {
            int col = nBase + wn*32 + nf*8 + tig*2;
            float c0 = acc[mf][nf][0], c1 = acc[mf][nf][1];
            float c2 = acc[mf][nf][2], c3 = acc[mf][nf][3];
            if (bias) {
                int cb = col & 63;
                int s0 = row0 & (SS-1), s1 = (row0+8) & (SS-1);
                c0 += bias[cb*SS + s0];     c1 += bias[(cb+1)*SS + s0];
                c2 += bias[cb*SS + s1];     c3 += bias[(cb+1)*SS + s1];
            }
            *(float2*)&C[(size_t)row0*DD + col]     = make_float2(c0, c1);
            *(float2*)&C[(size_t)(row0+8)*DD + col] = make_float2(c2, c3);
        }
    }
#undef LOAD_CHUNK
}

// ---------------------------------------------------------------------------
// causal flash attention (fp32 SIMT); writes H as bf16 hi/lo
// ---------------------------------------------------------------------------
__global__ void attn_kernel()
{
    extern __shared__ float smf[];
    float* Qs = smf;                // 64*64
    float* Ks = Qs + 64*64;         // 64*65
    float* Vs = Ks + 64*65;         // 64*65
    float* Pb = Vs + 64*65;         // 64*64

    const int bh = blockIdx.x;
    const int qt = blockIdx.y;
    const int b = bh >> 3, h = bh & 7;
    const int t = threadIdx.x;
    const int warp = t >> 5, lane = t & 31;

    const float* Qg = gC + (size_t)0*MROWS*DD + (size_t)b * SS * DD + h * DHEAD;
    const float* Kg = gC + (size_t)1*MROWS*DD + (size_t)b * SS * DD + h * DHEAD;
    const float* Vg = gC + (size_t)2*MROWS*DD + (size_t)b * SS * DD + h * DHEAD;

    for (int idx = t; idx < 64*16; idx += 256) {
        int r = idx >> 4, c = (idx & 15) * 4;
        float4 q4 = *(const float4*)&Qg[(qt*64 + r) * DD + c];
        Qs[r*64 + c+0] = q4.x * 0.125f;
        Qs[r*64 + c+1] = q4.y * 0.125f;
        Qs[r*64 + c+2] = q4.z * 0.125f;
        Qs[r*64 + c+3] = q4.w * 0.125f;
    }

    float o0[8], o1[8], m[8], l[8];
#pragma unroll
    for (int r = 0; r < 8; r++) { o0[r]=0.f; o1[r]=0.f; m[r]=-1e30f; l[r]=0.f; }

    for (int kt = 0; kt <= qt; kt++) {
        __syncthreads();
        for (int idx = t; idx < 64*16; idx += 256) {
            int r = idx >> 4, c = (idx & 15) * 4;
            float4 k4 = *(const float4*)&Kg[(kt*64 + r) * DD + c];
            float4 v4 = *(const float4*)&Vg[(kt*64 + r) * DD + c];
            Ks[r*65 + c+0] = k4.x; Ks[r*65 + c+1] = k4.y;
            Ks[r*65 + c+2] = k4.z; Ks[r*65 + c+3] = k4.w;
            Vs[r*65 + c+0] = v4.x; Vs[r*65 + c+1] = v4.y;
            Vs[r*65 + c+2] = v4.z; Vs[r*65 + c+3] = v4.w;
        }
        __syncthreads();

        float s0[8], s1[8];
#pragma unroll
        for (int r = 0; r < 8; r++) { s0[r]=0.f; s1[r]=0.f; }
#pragma unroll 8
        for (int kk = 0; kk < 64; kk++) {
            float k0 = Ks[lane*65 + kk];
            float k1 = Ks[(lane+32)*65 + kk];
#pragma unroll
            for (int r = 0; r < 8; r++) {
                float qv = Qs[(warp*8 + r)*64 + kk];
                s0[r] += qv * k0;
                s1[r] += qv * k1;
            }
        }

        if (kt == qt) {
#pragma unroll
            for (int r = 0; r < 8; r++) {
                int qi = warp*8 + r;
                if (lane      > qi) s0[r] = -1e30f;
                if (lane + 32 > qi) s1[r] = -1e30f;
            }
        }

#pragma unroll
        for (int r = 0; r < 8; r++) {
            float mx = fmaxf(s0[r], s1[r]);
#pragma unroll
            for (int off = 16; off; off >>= 1)
                mx = fmaxf(mx, __shfl_xor_sync(0xffffffffu, mx, off));
            float mnew = fmaxf(m[r], mx);
            float alpha = __expf(m[r] - mnew);
            float p0 = __expf(s0[r] - mnew);
            float p1 = __expf(s1[r] - mnew);
            float ps = p0 + p1;
#pragma unroll
            for (int off = 16; off; off >>= 1)
                ps += __shfl_xor_sync(0xffffffffu, ps, off);
            l[r] = l[r] * alpha + ps;
            o0[r] *= alpha; o1[r] *= alpha;
            m[r] = mnew;
            Pb[(warp*8 + r)*64 + lane]      = p0;
            Pb[(warp*8 + r)*64 + lane + 32] = p1;
        }
        __syncwarp();

#pragma unroll 8
        for (int j = 0; j < 64; j++) {
            float v0 = Vs[j*65 + lane];
            float v1 = Vs[j*65 + lane + 32];
#pragma unroll
            for (int r = 0; r < 8; r++) {
                float pj = Pb[(warp*8 + r)*64 + j];
                o0[r] += pj * v0;
                o1[r] += pj * v1;
            }
        }
    }

    __nv_bfloat16* Hs = gHs + (size_t)(b * SS + qt * 64) * 1024 + h * DHEAD;
#pragma unroll
    for (int r = 0; r < 8; r++) {
        int row = warp*8 + r;
        float inv = 1.f / l[r];
        float va = o0[r] * inv;
        float vb = o1[r] * inv;
        __nv_bfloat16 ha = __float2bfloat16(va);
        __nv_bfloat16 hb = __float2bfloat16(vb);
        Hs[(size_t)row*1024 + lane]            = ha;
        Hs[(size_t)row*1024 + lane + 32]       = hb;
        Hs[(size_t)row*1024 + 512 + lane]      = __float2bfloat16(va - __bfloat162float(ha));
        Hs[(size_t)row*1024 + 512 + lane + 32] = __float2bfloat16(vb - __bfloat162float(hb));
    }
}

// ---------------------------------------------------------------------------
extern "C" void kernel_launch(void* const* d_in, const int* in_sizes, int n_in,
                              void* d_out, int out_size)
{
    const float* xs  = (const float*)d_in[0];
    const float* xt  = (const float*)d_in[1];
    const float* Wqs = (const float*)d_in[2];
    const float* Wks = (const float*)d_in[3];
    const float* Wvs = (const float*)d_in[4];
    const float* Wqt = (const float*)d_in[5];
    const float* Wkt = (const float*)d_in[6];
    const float* Wvt = (const float*)d_in[7];
    const float* WKb = (const float*)d_in[8];
    const float* Wo  = (const float*)d_in[9];
    float* out = (float*)d_out;

    const int GEMM_SMEM = 4 * 128 * SROW * (int)sizeof(__nv_bfloat16);   // 73728
    const int ATTN_SMEM = (64*64 + 64*65 + 64*65 + 64*64) * (int)sizeof(float);
    cudaFuncSetAttribute(mma_gemm,    cudaFuncAttributeMaxDynamicSharedMemorySize, GEMM_SMEM);
    cudaFuncSetAttribute(attn_kernel, cudaFuncAttributeMaxDynamicSharedMemorySize, ATTN_SMEM);

    prep_A<<<MROWS, 512>>>(xs, xt);
    prep_W<<<(3*512*3072)/256, 256>>>(Wqs, Wks, Wvs, Wqt, Wkt, Wvt);
    prep_Wo<<<(512*1536)/256, 256>>>(Wo);

    mma_gemm<<<dim3(4, 64, 3), 256, GEMM_SMEM>>>(0, nullptr, WKb);   // QKV (+bias on z=1)
    attn_kernel<<<dim3(BB*NHEADS, SS/64), 256, ATTN_SMEM>>>();
    mma_gemm<<<dim3(4, 64, 1), 256, GEMM_SMEM>>>(1, out, WKb);       // out = H @ Wo
}

// round 4
// speedup vs baseline: 2.5241x; 1.4844x over previous
#include <cuda_runtime.h>
#include <cuda_bf16.h>
#include <cstdint>

#define BB 8
#define SS 1024
#define DD 512
#define NHEADS 8
#define DHEAD 64
#define MROWS (BB*SS)   // 8192

// ---------------- scratch (no allocation allowed) ----------------
__device__ float gC[(size_t)3*MROWS*DD];                 // Q, K_eff, V (fp32)
__device__ __nv_bfloat16 gA[(size_t)MROWS*2048];         // [xs_h | xt_h | xs_l | xt_l]
__device__ __nv_bfloat16 gHs[(size_t)MROWS*1024];        // [H_h | H_l]
__device__ __nv_bfloat16 gBt[(size_t)3*512*3072];        // per-z W_big^T  [n][k]
__device__ __nv_bfloat16 gWoT[(size_t)512*1536];         // Wo_big^T [n][k]

// ---------------- warp-mma helpers (sm_80+ ISA, plain sm_103 OK) ------------
__device__ __forceinline__ void ldsm4(uint32_t* r, uint32_t addr)
{
    asm volatile("ldmatrix.sync.aligned.m8n8.x4.shared.b16 {%0,%1,%2,%3}, [%4];"
        : "=r"(r[0]), "=r"(r[1]), "=r"(r[2]), "=r"(r[3]) : "r"(addr));
}

__device__ __forceinline__ void ldsm4t(uint32_t* r, uint32_t addr)
{
    asm volatile("ldmatrix.sync.aligned.m8n8.x4.trans.shared.b16 {%0,%1,%2,%3}, [%4];"
        : "=r"(r[0]), "=r"(r[1]), "=r"(r[2]), "=r"(r[3]) : "r"(addr));
}

__device__ __forceinline__ void mma16816(float* c, const uint32_t* a, const uint32_t* b)
{
    asm volatile(
        "mma.sync.aligned.m16n8k16.row.col.f32.bf16.bf16.f32 "
        "{%0,%1,%2,%3}, {%4,%5,%6,%7}, {%8,%9}, {%0,%1,%2,%3};"
        : "+f"(c[0]), "+f"(c[1]), "+f"(c[2]), "+f"(c[3])
        : "r"(a[0]), "r"(a[1]), "r"(a[2]), "r"(a[3]), "r"(b[0]), "r"(b[1]));
}

// split a float2 into packed bf16 hi pair + bf16 residual pair (low half = .x)
__device__ __forceinline__ void split2(float2 v, uint32_t& hi, uint32_t& lo)
{
    __nv_bfloat16 hx = __float2bfloat16(v.x);
    __nv_bfloat16 hy = __float2bfloat16(v.y);
    float rx = v.x - __bfloat162float(hx);
    float ry = v.y - __bfloat162float(hy);
    hi = ((uint32_t)__bfloat16_as_ushort(hy) << 16) | (uint32_t)__bfloat16_as_ushort(hx);
    lo = ((uint32_t)__bfloat16_as_ushort(__float2bfloat16(ry)) << 16)
       | (uint32_t)__bfloat16_as_ushort(__float2bfloat16(rx));
}

// ---------------------------------------------------------------------------
// prep kernels: bf16 hi/lo splits
// ---------------------------------------------------------------------------
__global__ void prep_A(const float* __restrict__ xs, const float* __restrict__ xt)
{
    int r = blockIdx.x;
    int c = threadIdx.x;            // 512 threads
    float a = xs[(size_t)r*DD + c];
    float b = xt[(size_t)r*DD + c];
    __nv_bfloat16 ah = __float2bfloat16(a);
    __nv_bfloat16 bh = __float2bfloat16(b);
    __nv_bfloat16* row = gA + (size_t)r*2048;
    row[c]        = ah;
    row[512 + c]  = bh;
    row[1024 + c] = __float2bfloat16(a - __bfloat162float(ah));
    row[1536 + c] = __float2bfloat16(b - __bfloat162float(bh));
}

__global__ void prep_W(const float* __restrict__ Wqs, const float* __restrict__ Wks,
                       const float* __restrict__ Wvs, const float* __restrict__ Wqt,
                       const float* __restrict__ Wkt, const float* __restrict__ Wvt)
{
    int idx = blockIdx.x * 256 + threadIdx.x;   // 3*512*3072 total
    int z   = idx / (512*3072);
    int rem = idx % (512*3072);
    int n   = rem / 3072;
    int k   = rem % 3072;
    const float* W1 = (z==0) ? Wqs : ((z==1) ? Wks : Wvs);
    const float* W2 = (z==0) ? Wqt : ((z==1) ? Wkt : Wvt);
    int kh = k >> 9, ks = k & 511;
    const float* M = (kh & 1) ? W2 : W1;
    float x = M[(size_t)ks*DD + n];
    __nv_bfloat16 v;
    if (kh < 4) v = __float2bfloat16(x);
    else {
        __nv_bfloat16 h = __float2bfloat16(x);
        v = __float2bfloat16(x - __bfloat162float(h));
    }
    gBt[idx] = v;
}

__global__ void prep_Wo(const float* __restrict__ Wo)
{
    int idx = blockIdx.x * 256 + threadIdx.x;   // 512*1536 total
    int n = idx / 1536;
    int k = idx % 1536;
    int kh = k >> 9, ks = k & 511;
    float x = Wo[(size_t)ks*DD + n];
    __nv_bfloat16 v;
    if (kh < 2) v = __float2bfloat16(x);
    else {
        __nv_bfloat16 h = __float2bfloat16(x);
        v = __float2bfloat16(x - __bfloat162float(h));
    }
    gWoT[idx] = v;
}

// ---------------------------------------------------------------------------
// bf16 mma.sync GEMM (unchanged from round 3)
// ---------------------------------------------------------------------------
#define SROW 72

__global__ __launch_bounds__(256)
void mma_gemm(int mode, float* __restrict__ outp, const float* __restrict__ WKb)
{
    extern __shared__ __nv_bfloat16 sm[];
    __nv_bfloat16* sA = sm;                    // [2][128][SROW]
    __nv_bfloat16* sB = sm + 2*128*SROW;       // [2][128][SROW]

    const __nv_bfloat16* A;
    const __nv_bfloat16* Bt;
    float* C;
    const float* bias = nullptr;
    int aW, remapC, kEff, nChunks;
    const int z = blockIdx.z;
    if (mode == 0) {
        A = gA; aW = 2048; remapC = 32; kEff = 3072; nChunks = 48;
        Bt = gBt + (size_t)z * 512 * 3072;
        C  = gC  + (size_t)z * MROWS * DD;
        if (z == 1) bias = WKb;
    } else {
        A = gHs; aW = 1024; remapC = 16; kEff = 1536; nChunks = 24;
        Bt = gWoT;
        C  = outp;
    }

    const int mBase = blockIdx.y * 128;
    const int nBase = blockIdx.x * 128;
    const int t    = threadIdx.x;
    const int warp = t >> 5;
    const int lane = t & 31;
    const int wm   = warp >> 2;
    const int wn   = warp & 3;

    const uint32_t sAu = (uint32_t)__cvta_generic_to_shared(sA);
    const uint32_t sBu = (uint32_t)__cvta_generic_to_shared(sB);

    const int ldRow = t >> 3;
    const int ldSeg = t & 7;

    float acc[4][4][4];
#pragma unroll
    for (int i = 0; i < 4; i++)
#pragma unroll
        for (int j = 0; j < 4; j++)
#pragma unroll
            for (int q = 0; q < 4; q++) acc[i][j][q] = 0.f;

#define LOAD_CHUNK(cc, buf) do { \
    int acol_ = (((cc) < remapC) ? (cc) : ((cc) - remapC)) << 6; \
    const __nv_bfloat16* Ag_ = A + (size_t)(mBase + ldRow) * aW + acol_ + ldSeg * 8; \
    const __nv_bfloat16* Bg_ = Bt + (size_t)(nBase + ldRow) * kEff + (size_t)(cc) * 64 + ldSeg * 8; \
    uint32_t da_ = sAu + ((buf)*128*SROW + ldRow*SROW + ldSeg*8) * 2; \
    uint32_t db_ = sBu + ((buf)*128*SROW + ldRow*SROW + ldSeg*8) * 2; \
    _Pragma("unroll") \
    for (int rr_ = 0; rr_ < 4; rr_++) { \
        asm volatile("cp.async.cg.shared.global [%0], [%1], 16;" \
            :: "r"(da_ + rr_*32*SROW*2), "l"(__cvta_generic_to_global((const void*)(Ag_ + (size_t)rr_*32*aW)))); \
        asm volatile("cp.async.cg.shared.global [%0], [%1], 16;" \
            :: "r"(db_ + rr_*32*SROW*2), "l"(__cvta_generic_to_global((const void*)(Bg_ + (size_t)rr_*32*kEff)))); \
    } \
    asm volatile("cp.async.commit_group;" ::: "memory"); \
} while (0)

    LOAD_CHUNK(0, 0);

    const int aRowL = wm*64 + (lane & 15);
    const int aColL = (lane >> 4) << 3;
    const int bRowL = wn*32 + ((lane >> 4) << 3) + (lane & 7);
    const int bColL = ((lane >> 3) & 1) << 3;

    for (int c = 0; c < nChunks; c++) {
        const int buf = c & 1;
        if (c + 1 < nChunks) LOAD_CHUNK(c + 1, buf ^ 1);
        if (c + 1 < nChunks) { asm volatile("cp.async.wait_group 1;" ::: "memory"); }
        else                 { asm volatile("cp.async.wait_group 0;" ::: "memory"); }
        __syncthreads();

        const uint32_t aB = sAu + (buf*128*SROW) * 2;
        const uint32_t bB = sBu + (buf*128*SROW) * 2;
#pragma unroll
        for (int ks = 0; ks < 4; ks++) {
            uint32_t afr[4][4];
#pragma unroll
            for (int mf = 0; mf < 4; mf++)
                ldsm4(afr[mf], aB + (((aRowL + mf*16) * SROW) + ks*16 + aColL) * 2);
            uint32_t bfr[4][2];
#pragma unroll
            for (int nfp = 0; nfp < 2; nfp++) {
                uint32_t r4[4];
                ldsm4(r4, bB + (((bRowL + nfp*16) * SROW) + ks*16 + bColL) * 2);
                bfr[nfp*2+0][0] = r4[0]; bfr[nfp*2+0][1] = r4[1];
                bfr[nfp*2+1][0] = r4[2]; bfr[nfp*2+1][1] = r4[3];
            }
#pragma unroll
            for (int mf = 0; mf < 4; mf++)
#pragma unroll
                for (int nf = 0; nf < 4; nf++)
                    mma16816(acc[mf][nf], afr[mf], bfr[nf]);
        }
        __syncthreads();
    }

    const int g   = lane >> 2;
    const int tig = lane & 3;
#pragma unroll
    for (int mf = 0; mf < 4; mf++) {
        int row0 = mBase + wm*64 + mf*16 + g;
#pragma unroll
        for (int nf = 0; nf < 4; nf++) {
            int col = nBase + wn*32 + nf*8 + tig*2;
            float c0 = acc[mf][nf][0], c1 = acc[mf][nf][1];
            float c2 = acc[mf][nf][2], c3 = acc[mf][nf][3];
            if (bias) {
                int cb = col & 63;
                int s0 = row0 & (SS-1), s1 = (row0+8) & (SS-1);
                c0 += bias[cb*SS + s0];     c1 += bias[(cb+1)*SS + s0];
                c2 += bias[cb*SS + s1];     c3 += bias[(cb+1)*SS + s1];
            }
            *(float2*)&C[(size_t)row0*DD + col]     = make_float2(c0, c1);
            *(float2*)&C[(size_t)(row0+8)*DD + col] = make_float2(c2, c3);
        }
    }
#undef LOAD_CHUNK
}

// ---------------------------------------------------------------------------
// tensor-core causal flash attention, split-bf16 (3-term) QK^T and PV.
// Block = (bh, qtile of 128 rows); 8 warps x 16 rows. K-tiles of 64.
// ---------------------------------------------------------------------------
__global__ __launch_bounds__(256, 1) void attn_mma()
{
    __shared__ __nv_bfloat16 sKh[64*72];
    __shared__ __nv_bfloat16 sKl[64*72];
    __shared__ __nv_bfloat16 sVh[64*72];
    __shared__ __nv_bfloat16 sVl[64*72];

    const int bx = blockIdx.x;
    const int qt = 7 - (bx >> 6);            // big tiles first
    const int bh = bx & 63;
    const int b = bh >> 3, h = bh & 7;
    const int t = threadIdx.x, warp = t >> 5, lane = t & 31;
    const int g = lane >> 2, tig = lane & 3;

    const float* Qg = gC + (size_t)(b*SS)*DD + h*DHEAD;
    const float* Kg = gC + (size_t)MROWS*DD + (size_t)(b*SS)*DD + h*DHEAD;
    const float* Vg = gC + (size_t)(2*MROWS)*DD + (size_t)(b*SS)*DD + h*DHEAD;

    const int rloc0 = qt*128 + warp*16 + g;  // sequence-local q rows of this thread
    const int rloc1 = rloc0 + 8;

    // ---- Q fragments (hi/lo), scaled by 1/sqrt(dh)=0.125
    uint32_t qh[4][4], ql[4][4];
    {
        const float* Q0 = Qg + (size_t)rloc0 * DD;
        const float* Q1 = Qg + (size_t)rloc1 * DD;
#pragma unroll
        for (int s = 0; s < 4; s++) {
            float2 x0 = *(const float2*)&Q0[s*16 + 2*tig];
            float2 x1 = *(const float2*)&Q1[s*16 + 2*tig];
            float2 x2 = *(const float2*)&Q0[s*16 + 8 + 2*tig];
            float2 x3 = *(const float2*)&Q1[s*16 + 8 + 2*tig];
            x0.x *= 0.125f; x0.y *= 0.125f; x1.x *= 0.125f; x1.y *= 0.125f;
            x2.x *= 0.125f; x2.y *= 0.125f; x3.x *= 0.125f; x3.y *= 0.125f;
            split2(x0, qh[s][0], ql[s][0]);
            split2(x1, qh[s][1], ql[s][1]);
            split2(x2, qh[s][2], ql[s][2]);
            split2(x3, qh[s][3], ql[s][3]);
        }
    }

    float o[8][4];
#pragma unroll
    for (int nf = 0; nf < 8; nf++)
#pragma unroll
        for (int j = 0; j < 4; j++) o[nf][j] = 0.f;
    float m0 = -1e30f, m1 = -1e30f, l0 = 0.f, l1 = 0.f;

    // K/V tile prefetch registers
    const int lr = t >> 2;          // 0..63 key row
    const int lc = (t & 3) * 16;    // col base
    float4 kf[4], vf[4];

#define FETCH_KV(kt_) do { \
    const float* Kp_ = Kg + (size_t)((kt_)*64 + lr)*DD + lc; \
    const float* Vp_ = Vg + (size_t)((kt_)*64 + lr)*DD + lc; \
    _Pragma("unroll") \
    for (int i_ = 0; i_ < 4; i_++) { \
        kf[i_] = *(const float4*)(Kp_ + i_*4); \
        vf[i_] = *(const float4*)(Vp_ + i_*4); \
    } \
} while (0)

    // ldmatrix base addresses
    const uint32_t khB = (uint32_t)__cvta_generic_to_shared(sKh)
        + ((((lane>>4)<<3 | (lane&7))*72 + (((lane>>3)&1)<<3)) * 2);
    const uint32_t klB = (uint32_t)__cvta_generic_to_shared(sKl)
        + ((((lane>>4)<<3 | (lane&7))*72 + (((lane>>3)&1)<<3)) * 2);
    const uint32_t vhB = (uint32_t)__cvta_generic_to_shared(sVh)
        + (((lane&15)*72 + ((lane>>4)<<3)) * 2);
    const uint32_t vlB = (uint32_t)__cvta_generic_to_shared(sVl)
        + (((lane&15)*72 + ((lane>>4)<<3)) * 2);

    const int nkt = 2*qt + 2;
    FETCH_KV(0);

    for (int kt = 0; kt < nkt; kt++) {
        __syncthreads();
        // convert + store tile to smem (hi/lo)
#pragma unroll
        for (int i = 0; i < 4; i++) {
            uint32_t h0, lo0, h1, lo1;
            split2(make_float2(kf[i].x, kf[i].y), h0, lo0);
            split2(make_float2(kf[i].z, kf[i].w), h1, lo1);
            *(uint2*)&sKh[lr*72 + lc + i*4] = make_uint2(h0, h1);
            *(uint2*)&sKl[lr*72 + lc + i*4] = make_uint2(lo0, lo1);
            split2(make_float2(vf[i].x, vf[i].y), h0, lo0);
            split2(make_float2(vf[i].z, vf[i].w), h1, lo1);
            *(uint2*)&sVh[lr*72 + lc + i*4] = make_uint2(h0, h1);
            *(uint2*)&sVl[lr*72 + lc + i*4] = make_uint2(lo0, lo1);
        }
        __syncthreads();
        if (kt + 1 < nkt) FETCH_KV(kt + 1);

        const bool active = (qt*128 + warp*16 + 15) >= kt*64;
        if (active) {
            // ---- scores S = Qh Kh + Ql Kh + Qh Kl
            float s[8][4];
#pragma unroll
            for (int nf = 0; nf < 8; nf++)
#pragma unroll
                for (int j = 0; j < 4; j++) s[nf][j] = 0.f;

#pragma unroll
            for (int nfp = 0; nfp < 4; nfp++) {
#pragma unroll
                for (int ks = 0; ks < 4; ks++) {
                    uint32_t kr[4];
                    ldsm4(kr, khB + (uint32_t)((nfp*16*72 + ks*16) * 2));
                    mma16816(s[2*nfp],   qh[ks], kr);
                    mma16816(s[2*nfp+1], qh[ks], kr + 2);
                    mma16816(s[2*nfp],   ql[ks], kr);
                    mma16816(s[2*nfp+1], ql[ks], kr + 2);
                    ldsm4(kr, klB + (uint32_t)((nfp*16*72 + ks*16) * 2));
                    mma16816(s[2*nfp],   qh[ks], kr);
                    mma16816(s[2*nfp+1], qh[ks], kr + 2);
                }
            }

            // ---- causal mask (only tiles touching the diagonal block)
            if (kt >= 2*qt) {
                const int key0 = kt*64;
#pragma unroll
                for (int nf = 0; nf < 8; nf++) {
                    int kc = key0 + nf*8 + 2*tig;
                    if (kc     > rloc0) s[nf][0] = -1e30f;
                    if (kc + 1 > rloc0) s[nf][1] = -1e30f;
                    if (kc     > rloc1) s[nf][2] = -1e30f;
                    if (kc + 1 > rloc1) s[nf][3] = -1e30f;
                }
            }

            // ---- online softmax (rows g, g+8; quad reduction)
            float mx0 = -1e30f, mx1 = -1e30f;
#pragma unroll
            for (int nf = 0; nf < 8; nf++) {
                mx0 = fmaxf(mx0, fmaxf(s[nf][0], s[nf][1]));
                mx1 = fmaxf(mx1, fmaxf(s[nf][2], s[nf][3]));
            }
            mx0 = fmaxf(mx0, __shfl_xor_sync(0xffffffffu, mx0, 1));
            mx0 = fmaxf(mx0, __shfl_xor_sync(0xffffffffu, mx0, 2));
            mx1 = fmaxf(mx1, __shfl_xor_sync(0xffffffffu, mx1, 1));
            mx1 = fmaxf(mx1, __shfl_xor_sync(0xffffffffu, mx1, 2));
            float mn0 = fmaxf(m0, mx0), mn1 = fmaxf(m1, mx1);
            float a0 = __expf(m0 - mn0), a1 = __expf(m1 - mn1);
            m0 = mn0; m1 = mn1;
            float sum0 = 0.f, sum1 = 0.f;
#pragma unroll
            for (int nf = 0; nf < 8; nf++) {
                s[nf][0] = __expf(s[nf][0] - mn0);
                s[nf][1] = __expf(s[nf][1] - mn0);
                s[nf][2] = __expf(s[nf][2] - mn1);
                s[nf][3] = __expf(s[nf][3] - mn1);
                sum0 += s[nf][0] + s[nf][1];
                sum1 += s[nf][2] + s[nf][3];
            }
            sum0 += __shfl_xor_sync(0xffffffffu, sum0, 1);
            sum0 += __shfl_xor_sync(0xffffffffu, sum0, 2);
            sum1 += __shfl_xor_sync(0xffffffffu, sum1, 1);
            sum1 += __shfl_xor_sync(0xffffffffu, sum1, 2);
            l0 = l0*a0 + sum0;
            l1 = l1*a1 + sum1;
#pragma unroll
            for (int nf = 0; nf < 8; nf++) {
                o[nf][0] *= a0; o[nf][1] *= a0;
                o[nf][2] *= a1; o[nf][3] *= a1;
            }

            // ---- O += Ph Vh + Ph Vl + Pl Vh
#pragma unroll
            for (int sk = 0; sk < 4; sk++) {
                uint32_t ph[4], pl[4];
                split2(make_float2(s[2*sk][0],   s[2*sk][1]),   ph[0], pl[0]);
                split2(make_float2(s[2*sk][2],   s[2*sk][3]),   ph[1], pl[1]);
                split2(make_float2(s[2*sk+1][0], s[2*sk+1][1]), ph[2], pl[2]);
                split2(make_float2(s[2*sk+1][2], s[2*sk+1][3]), ph[3], pl[3]);
#pragma unroll
                for (int nb = 0; nb < 4; nb++) {
                    uint32_t vh4[4], vl4[4];
                    ldsm4t(vh4, vhB + (uint32_t)((sk*16*72 + nb*16) * 2));
                    ldsm4t(vl4, vlB + (uint32_t)((sk*16*72 + nb*16) * 2));
                    mma16816(o[2*nb],   ph, vh4);
                    mma16816(o[2*nb+1], ph, vh4 + 2);
                    mma16816(o[2*nb],   ph, vl4);
                    mma16816(o[2*nb+1], ph, vl4 + 2);
                    mma16816(o[2*nb],   pl, vh4);
                    mma16816(o[2*nb+1], pl, vh4 + 2);
                }
            }
        }
    }

    // ---- epilogue: normalize, write bf16 hi/lo into gHs
    {
        float i0 = 1.f / l0, i1 = 1.f / l1;
        __nv_bfloat16* base0 = gHs + (size_t)(b*SS + rloc0) * 1024;
        __nv_bfloat16* base1 = gHs + (size_t)(b*SS + rloc1) * 1024;
#pragma unroll
        for (int nf = 0; nf < 8; nf++) {
            int col = h*64 + nf*8 + 2*tig;
            uint32_t hi, lo;
            split2(make_float2(o[nf][0]*i0, o[nf][1]*i0), hi, lo);
            *(uint32_t*)&base0[col]       = hi;
            *(uint32_t*)&base0[512 + col] = lo;
            split2(make_float2(o[nf][2]*i1, o[nf][3]*i1), hi, lo);
            *(uint32_t*)&base1[col]       = hi;
            *(uint32_t*)&base1[512 + col] = lo;
        }
    }
#undef FETCH_KV
}

// ---------------------------------------------------------------------------
extern "C" void kernel_launch(void* const* d_in, const int* in_sizes, int n_in,
                              void* d_out, int out_size)
{
    const float* xs  = (const float*)d_in[0];
    const float* xt  = (const float*)d_in[1];
    const float* Wqs = (const float*)d_in[2];
    const float* Wks = (const float*)d_in[3];
    const float* Wvs = (const float*)d_in[4];
    const float* Wqt = (const float*)d_in[5];
    const float* Wkt = (const float*)d_in[6];
    const float* Wvt = (const float*)d_in[7];
    const float* WKb = (const float*)d_in[8];
    const float* Wo  = (const float*)d_in[9];
    float* out = (float*)d_out;

    const int GEMM_SMEM = 4 * 128 * SROW * (int)sizeof(__nv_bfloat16);   // 73728
    cudaFuncSetAttribute(mma_gemm, cudaFuncAttributeMaxDynamicSharedMemorySize, GEMM_SMEM);

    prep_A<<<MROWS, 512>>>(xs, xt);
    prep_W<<<(3*512*3072)/256, 256>>>(Wqs, Wks, Wvs, Wqt, Wkt, Wvt);
    prep_Wo<<<(512*1536)/256, 256>>>(Wo);

    mma_gemm<<<dim3(4, 64, 3), 256, GEMM_SMEM>>>(0, nullptr, WKb);   // QKV (+bias on z=1)
    attn_mma<<<512, 256>>>();
    mma_gemm<<<dim3(4, 64, 1), 256, GEMM_SMEM>>>(1, out, WKb);       // out = H @ Wo
}

// round 5
// speedup vs baseline: 2.8036x; 1.1107x over previous
#include <cuda_runtime.h>
#include <cuda_bf16.h>
#include <cstdint>

#define BB 8
#define SS 1024
#define DD 512
#define NHEADS 8
#define DHEAD 64
#define MROWS (BB*SS)   // 8192

// ---------------- scratch (no allocation allowed) ----------------
__device__ float gC[(size_t)3*MROWS*DD];                 // Q, K_eff, V (fp32)
__device__ __nv_bfloat16 gA[(size_t)MROWS*2048];         // [xs_h | xt_h | xs_l | xt_l]
__device__ __nv_bfloat16 gHs[(size_t)MROWS*1024];        // [H_h | H_l]
__device__ __nv_bfloat16 gBt[(size_t)3*512*3072];        // per-z W_big^T  [n][k]
__device__ __nv_bfloat16 gWoT[(size_t)512*1536];         // Wo_big^T [n][k]

// ---------------- warp-mma helpers ----------------
__device__ __forceinline__ void ldsm4(uint32_t* r, uint32_t addr)
{
    asm volatile("ldmatrix.sync.aligned.m8n8.x4.shared.b16 {%0,%1,%2,%3}, [%4];"
        : "=r"(r[0]), "=r"(r[1]), "=r"(r[2]), "=r"(r[3]) : "r"(addr));
}

__device__ __forceinline__ void ldsm4t(uint32_t* r, uint32_t addr)
{
    asm volatile("ldmatrix.sync.aligned.m8n8.x4.trans.shared.b16 {%0,%1,%2,%3}, [%4];"
        : "=r"(r[0]), "=r"(r[1]), "=r"(r[2]), "=r"(r[3]) : "r"(addr));
}

__device__ __forceinline__ void mma16816(float* c, const uint32_t* a, const uint32_t* b)
{
    asm volatile(
        "mma.sync.aligned.m16n8k16.row.col.f32.bf16.bf16.f32 "
        "{%0,%1,%2,%3}, {%4,%5,%6,%7}, {%8,%9}, {%0,%1,%2,%3};"
        : "+f"(c[0]), "+f"(c[1]), "+f"(c[2]), "+f"(c[3])
        : "r"(a[0]), "r"(a[1]), "r"(a[2]), "r"(a[3]), "r"(b[0]), "r"(b[1]));
}

__device__ __forceinline__ void split2(float2 v, uint32_t& hi, uint32_t& lo)
{
    __nv_bfloat16 hx = __float2bfloat16(v.x);
    __nv_bfloat16 hy = __float2bfloat16(v.y);
    float rx = v.x - __bfloat162float(hx);
    float ry = v.y - __bfloat162float(hy);
    hi = ((uint32_t)__bfloat16_as_ushort(hy) << 16) | (uint32_t)__bfloat16_as_ushort(hx);
    lo = ((uint32_t)__bfloat16_as_ushort(__float2bfloat16(ry)) << 16)
       | (uint32_t)__bfloat16_as_ushort(__float2bfloat16(rx));
}

// ---------------------------------------------------------------------------
// prep kernels
// ---------------------------------------------------------------------------
__global__ void prep_A(const float* __restrict__ xs, const float* __restrict__ xt)
{
    int r = blockIdx.x;
    int c = threadIdx.x;
    float a = xs[(size_t)r*DD + c];
    float b = xt[(size_t)r*DD + c];
    __nv_bfloat16 ah = __float2bfloat16(a);
    __nv_bfloat16 bh = __float2bfloat16(b);
    __nv_bfloat16* row = gA + (size_t)r*2048;
    row[c]        = ah;
    row[512 + c]  = bh;
    row[1024 + c] = __float2bfloat16(a - __bfloat162float(ah));
    row[1536 + c] = __float2bfloat16(b - __bfloat162float(bh));
}

__global__ void prep_W(const float* __restrict__ Wqs, const float* __restrict__ Wks,
                       const float* __restrict__ Wvs, const float* __restrict__ Wqt,
                       const float* __restrict__ Wkt, const float* __restrict__ Wvt)
{
    int idx = blockIdx.x * 256 + threadIdx.x;
    int z   = idx / (512*3072);
    int rem = idx % (512*3072);
    int n   = rem / 3072;
    int k   = rem % 3072;
    const float* W1 = (z==0) ? Wqs : ((z==1) ? Wks : Wvs);
    const float* W2 = (z==0) ? Wqt : ((z==1) ? Wkt : Wvt);
    int kh = k >> 9, ks = k & 511;
    const float* M = (kh & 1) ? W2 : W1;
    float x = M[(size_t)ks*DD + n];
    __nv_bfloat16 v;
    if (kh < 4) v = __float2bfloat16(x);
    else {
        __nv_bfloat16 h = __float2bfloat16(x);
        v = __float2bfloat16(x - __bfloat162float(h));
    }
    gBt[idx] = v;
}

__global__ void prep_Wo(const float* __restrict__ Wo)
{
    int idx = blockIdx.x * 256 + threadIdx.x;
    int n = idx / 1536;
    int k = idx % 1536;
    int kh = k >> 9, ks = k & 511;
    float x = Wo[(size_t)ks*DD + n];
    __nv_bfloat16 v;
    if (kh < 2) v = __float2bfloat16(x);
    else {
        __nv_bfloat16 h = __float2bfloat16(x);
        v = __float2bfloat16(x - __bfloat162float(h));
    }
    gWoT[idx] = v;
}

// ---------------------------------------------------------------------------
// bf16 mma.sync GEMM, 3-stage cp.async pipeline, SW128-swizzled smem,
// ONE __syncthreads per K-chunk.  Block 128x128, warp tile 64x32, BK=64.
// Stage layout: stage s at s*32768: A tile [128][64] (16KB) then B tile (16KB).
// ---------------------------------------------------------------------------
__global__ __launch_bounds__(256)
void mma_gemm(int mode, float* __restrict__ outp, const float* __restrict__ WKb)
{
    extern __shared__ __nv_bfloat16 smg[];

    const __nv_bfloat16* A;
    const __nv_bfloat16* Bt;
    float* C;
    const float* bias = nullptr;
    int aW, remapC, kEff, nChunks;
    const int z = blockIdx.z;
    if (mode == 0) {
        A = gA; aW = 2048; remapC = 32; kEff = 3072; nChunks = 48;
        Bt = gBt + (size_t)z * 512 * 3072;
        C  = gC  + (size_t)z * MROWS * DD;
        if (z == 1) bias = WKb;
    } else {
        A = gHs; aW = 1024; remapC = 16; kEff = 1536; nChunks = 24;
        Bt = gWoT;
        C  = outp;
    }

    const int mBase = blockIdx.y * 128;
    const int nBase = blockIdx.x * 128;
    const int t    = threadIdx.x;
    const int warp = t >> 5;
    const int lane = t & 31;
    const int wm   = warp >> 2;
    const int wn   = warp & 3;

    const uint32_t sBase = (uint32_t)__cvta_generic_to_shared(smg);

    const int ldRow = t >> 3;          // 0..31
    const int ldSeg = t & 7;           // 16B segment
    // swizzled dst offset within a [128][64]bf16 tile (bytes)
    const uint32_t ldSw = ((uint32_t)ldRow << 7)
                        + (((uint32_t)ldSeg << 4) ^ (((uint32_t)ldRow & 7) << 4));

    float acc[4][4][4];
#pragma unroll
    for (int i = 0; i < 4; i++)
#pragma unroll
        for (int j = 0; j < 4; j++)
#pragma unroll
            for (int q = 0; q < 4; q++) acc[i][j][q] = 0.f;

#define LOAD_CHUNK(cc, buf) do { \
    int acol_ = (((cc) < remapC) ? (cc) : ((cc) - remapC)) << 6; \
    const __nv_bfloat16* Ag_ = A + (size_t)(mBase + ldRow) * aW + acol_ + ldSeg * 8; \
    const __nv_bfloat16* Bg_ = Bt + (size_t)(nBase + ldRow) * kEff + (size_t)(cc) * 64 + ldSeg * 8; \
    uint32_t da_ = sBase + (buf)*32768u + ldSw; \
    uint32_t db_ = da_ + 16384u; \
    _Pragma("unroll") \
    for (int rr_ = 0; rr_ < 4; rr_++) { \
        asm volatile("cp.async.cg.shared.global [%0], [%1], 16;" \
            :: "r"(da_ + rr_*4096u), "l"(__cvta_generic_to_global((const void*)(Ag_ + (size_t)rr_*32*aW)))); \
        asm volatile("cp.async.cg.shared.global [%0], [%1], 16;" \
            :: "r"(db_ + rr_*4096u), "l"(__cvta_generic_to_global((const void*)(Bg_ + (size_t)rr_*32*kEff)))); \
    } \
    asm volatile("cp.async.commit_group;" ::: "memory"); \
} while (0)

    LOAD_CHUNK(0, 0);
    LOAD_CHUNK(1, 1);

    // ldmatrix per-thread geometry
    const int aRowL = wm*64 + (lane & 15);
    const int aColB = (((lane >> 4) << 3)) * 2;            // byte col base
    const uint32_t aSw = ((uint32_t)aRowL & 7) << 4;
    const int bRowL = wn*32 + ((lane >> 4) << 3) + (lane & 7);
    const int bColB = ((((lane >> 3) & 1) << 3)) * 2;
    const uint32_t bSw = ((uint32_t)bRowL & 7) << 4;

    for (int c = 0; c < nChunks; c++) {
        const int buf = c % 3;
        if (c + 1 < nChunks) { asm volatile("cp.async.wait_group 1;" ::: "memory"); }
        else                 { asm volatile("cp.async.wait_group 0;" ::: "memory"); }
        __syncthreads();
        if (c + 2 < nChunks) LOAD_CHUNK(c + 2, (c + 2) % 3);

        const uint32_t aB = sBase + buf*32768u;
        const uint32_t bB = aB + 16384u;
#pragma unroll
        for (int ks = 0; ks < 4; ks++) {
            const uint32_t kb = (uint32_t)(ks << 5);   // ks*16 elems = 32 bytes
            uint32_t afr[4][4];
#pragma unroll
            for (int mf = 0; mf < 4; mf++)
                ldsm4(afr[mf], aB + (uint32_t)((aRowL + mf*16) << 7) + ((kb + aColB) ^ aSw));
            uint32_t bfr[4][2];
#pragma unroll
            for (int nfp = 0; nfp < 2; nfp++) {
                uint32_t r4[4];
                ldsm4(r4, bB + (uint32_t)((bRowL + nfp*16) << 7) + ((kb + bColB) ^ bSw));
                bfr[nfp*2+0][0] = r4[0]; bfr[nfp*2+0][1] = r4[1];
                bfr[nfp*2+1][0] = r4[2]; bfr[nfp*2+1][1] = r4[3];
            }
#pragma unroll
            for (int mf = 0; mf < 4; mf++)
#pragma unroll
                for (int nf = 0; nf < 4; nf++)
                    mma16816(acc[mf][nf], afr[mf], bfr[nf]);
        }
    }

    const int g   = lane >> 2;
    const int tig = lane & 3;
#pragma unroll
    for (int mf = 0; mf < 4; mf++) {
        int row0 = mBase + wm*64 + mf*16 + g;
#pragma unroll
        for (int nf = 0; nf < 4; nf++) {
            int col = nBase + wn*32 + nf*8 + tig*2;
            float c0 = acc[mf][nf][0], c1 = acc[mf][nf][1];
            float c2 = acc[mf][nf][2], c3 = acc[mf][nf][3];
            if (bias) {
                int cb = col & 63;
                int s0 = row0 & (SS-1), s1 = (row0+8) & (SS-1);
                c0 += bias[cb*SS + s0];     c1 += bias[(cb+1)*SS + s0];
                c2 += bias[cb*SS + s1];     c3 += bias[(cb+1)*SS + s1];
            }
            *(float2*)&C[(size_t)row0*DD + col]     = make_float2(c0, c1);
            *(float2*)&C[(size_t)(row0+8)*DD + col] = make_float2(c2, c3);
        }
    }
#undef LOAD_CHUNK
}

// ---------------------------------------------------------------------------
// tensor-core causal flash attention, split-bf16, double-buffered K/V smem,
// ONE __syncthreads per K-tile.
// ---------------------------------------------------------------------------
#define ATTN_BUF (4*64*72)   // bf16 elems per buffer (Kh,Kl,Vh,Vl)

__global__ __launch_bounds__(256, 1) void attn_mma()
{
    extern __shared__ __nv_bfloat16 sma[];   // [2][4][64*72]

    const int bx = blockIdx.x;
    const int qt = 7 - (bx >> 6);
    const int bh = bx & 63;
    const int b = bh >> 3, h = bh & 7;
    const int t = threadIdx.x, warp = t >> 5, lane = t & 31;
    const int g = lane >> 2, tig = lane & 3;

    const float* Qg = gC + (size_t)(b*SS)*DD + h*DHEAD;
    const float* Kg = gC + (size_t)MROWS*DD + (size_t)(b*SS)*DD + h*DHEAD;
    const float* Vg = gC + (size_t)(2*MROWS)*DD + (size_t)(b*SS)*DD + h*DHEAD;

    const int rloc0 = qt*128 + warp*16 + g;
    const int rloc1 = rloc0 + 8;

    uint32_t qh[4][4], ql[4][4];
    {
        const float* Q0 = Qg + (size_t)rloc0 * DD;
        const float* Q1 = Qg + (size_t)rloc1 * DD;
#pragma unroll
        for (int s = 0; s < 4; s++) {
            float2 x0 = *(const float2*)&Q0[s*16 + 2*tig];
            float2 x1 = *(const float2*)&Q1[s*16 + 2*tig];
            float2 x2 = *(const float2*)&Q0[s*16 + 8 + 2*tig];
            float2 x3 = *(const float2*)&Q1[s*16 + 8 + 2*tig];
            x0.x *= 0.125f; x0.y *= 0.125f; x1.x *= 0.125f; x1.y *= 0.125f;
            x2.x *= 0.125f; x2.y *= 0.125f; x3.x *= 0.125f; x3.y *= 0.125f;
            split2(x0, qh[s][0], ql[s][0]);
            split2(x1, qh[s][1], ql[s][1]);
            split2(x2, qh[s][2], ql[s][2]);
            split2(x3, qh[s][3], ql[s][3]);
        }
    }

    float o[8][4];
#pragma unroll
    for (int nf = 0; nf < 8; nf++)
#pragma unroll
        for (int j = 0; j < 4; j++) o[nf][j] = 0.f;
    float m0 = -1e30f, m1 = -1e30f, l0 = 0.f, l1 = 0.f;

    const int lr = t >> 2;
    const int lc = (t & 3) * 16;
    float4 kf[4], vf[4];

#define FETCH_KV(kt_) do { \
    const float* Kp_ = Kg + (size_t)((kt_)*64 + lr)*DD + lc; \
    const float* Vp_ = Vg + (size_t)((kt_)*64 + lr)*DD + lc; \
    _Pragma("unroll") \
    for (int i_ = 0; i_ < 4; i_++) { \
        kf[i_] = *(const float4*)(Kp_ + i_*4); \
        vf[i_] = *(const float4*)(Vp_ + i_*4); \
    } \
} while (0)

#define STORE_KV(buf_) do { \
    __nv_bfloat16* base_ = sma + (buf_)*ATTN_BUF; \
    _Pragma("unroll") \
    for (int i_ = 0; i_ < 4; i_++) { \
        uint32_t h0_, l0_, h1_, l1_; \
        split2(make_float2(kf[i_].x, kf[i_].y), h0_, l0_); \
        split2(make_float2(kf[i_].z, kf[i_].w), h1_, l1_); \
        *(uint2*)&base_[lr*72 + lc + i_*4]           = make_uint2(h0_, h1_); \
        *(uint2*)&base_[64*72 + lr*72 + lc + i_*4]   = make_uint2(l0_, l1_); \
        split2(make_float2(vf[i_].x, vf[i_].y), h0_, l0_); \
        split2(make_float2(vf[i_].z, vf[i_].w), h1_, l1_); \
        *(uint2*)&base_[2*64*72 + lr*72 + lc + i_*4] = make_uint2(h0_, h1_); \
        *(uint2*)&base_[3*64*72 + lr*72 + lc + i_*4] = make_uint2(l0_, l1_); \
    } \
} while (0)

    const uint32_t smB = (uint32_t)__cvta_generic_to_shared(sma);
    const uint32_t kFragOff = ((((lane>>4)<<3 | (lane&7))*72 + (((lane>>3)&1)<<3)) * 2);
    const uint32_t vFragOff = (((lane&15)*72 + ((lane>>4)<<3)) * 2);

    const int nkt = 2*qt + 2;
    FETCH_KV(0);
    STORE_KV(0);

    for (int kt = 0; kt < nkt; kt++) {
        __syncthreads();                       // buf[kt&1] complete
        if (kt + 1 < nkt) FETCH_KV(kt + 1);

        const uint32_t bufB = smB + (uint32_t)((kt & 1) * ATTN_BUF * 2);
        const bool active = (qt*128 + warp*16 + 15) >= kt*64;
        if (active) {
            float s[8][4];
#pragma unroll
            for (int nf = 0; nf < 8; nf++)
#pragma unroll
                for (int j = 0; j < 4; j++) s[nf][j] = 0.f;

            const uint32_t khB = bufB + kFragOff;
            const uint32_t klB = khB + 9216u;
#pragma unroll
            for (int nfp = 0; nfp < 4; nfp++) {
#pragma unroll
                for (int ks = 0; ks < 4; ks++) {
                    uint32_t kr[4];
                    ldsm4(kr, khB + (uint32_t)((nfp*16*72 + ks*16) * 2));
                    mma16816(s[2*nfp],   qh[ks], kr);
                    mma16816(s[2*nfp+1], qh[ks], kr + 2);
                    mma16816(s[2*nfp],   ql[ks], kr);
                    mma16816(s[2*nfp+1], ql[ks], kr + 2);
                    ldsm4(kr, klB + (uint32_t)((nfp*16*72 + ks*16) * 2));
                    mma16816(s[2*nfp],   qh[ks], kr);
                    mma16816(s[2*nfp+1], qh[ks], kr + 2);
                }
            }

            if (kt >= 2*qt) {
                const int key0 = kt*64;
#pragma unroll
                for (int nf = 0; nf < 8; nf++) {
                    int kc = key0 + nf*8 + 2*tig;
                    if (kc     > rloc0) s[nf][0] = -1e30f;
                    if (kc + 1 > rloc0) s[nf][1] = -1e30f;
                    if (kc     > rloc1) s[nf][2] = -1e30f;
                    if (kc + 1 > rloc1) s[nf][3] = -1e30f;
                }
            }

            float mx0 = -1e30f, mx1 = -1e30f;
#pragma unroll
            for (int nf = 0; nf < 8; nf++) {
                mx0 = fmaxf(mx0, fmaxf(s[nf][0], s[nf][1]));
                mx1 = fmaxf(mx1, fmaxf(s[nf][2], s[nf][3]));
            }
            mx0 = fmaxf(mx0, __shfl_xor_sync(0xffffffffu, mx0, 1));
            mx0 = fmaxf(mx0, __shfl_xor_sync(0xffffffffu, mx0, 2));
            mx1 = fmaxf(mx1, __shfl_xor_sync(0xffffffffu, mx1, 1));
            mx1 = fmaxf(mx1, __shfl_xor_sync(0xffffffffu, mx1, 2));
            float mn0 = fmaxf(m0, mx0), mn1 = fmaxf(m1, mx1);
            float a0 = __expf(m0 - mn0), a1 = __expf(m1 - mn1);
            m0 = mn0; m1 = mn1;
            float sum0 = 0.f, sum1 = 0.f;
#pragma unroll
            for (int nf = 0; nf < 8; nf++) {
                s[nf][0] = __expf(s[nf][0] - mn0);
                s[nf][1] = __expf(s[nf][1] - mn0);
                s[nf][2] = __expf(s[nf][2] - mn1);
                s[nf][3] = __expf(s[nf][3] - mn1);
                sum0 += s[nf][0] + s[nf][1];
                sum1 += s[nf][2] + s[nf][3];
            }
            sum0 += __shfl_xor_sync(0xffffffffu, sum0, 1);
            sum0 += __shfl_xor_sync(0xffffffffu, sum0, 2);
            sum1 += __shfl_xor_sync(0xffffffffu, sum1, 1);
            sum1 += __shfl_xor_sync(0xffffffffu, sum1, 2);
            l0 = l0*a0 + sum0;
            l1 = l1*a1 + sum1;
#pragma unroll
            for (int nf = 0; nf < 8; nf++) {
                o[nf][0] *= a0; o[nf][1] *= a0;
                o[nf][2] *= a1; o[nf][3] *= a1;
            }

            const uint32_t vhB = bufB + 18432u + vFragOff;
            const uint32_t vlB = vhB + 9216u;
#pragma unroll
            for (int sk = 0; sk < 4; sk++) {
                uint32_t ph[4], pl[4];
                split2(make_float2(s[2*sk][0],   s[2*sk][1]),   ph[0], pl[0]);
                split2(make_float2(s[2*sk][2],   s[2*sk][3]),   ph[1], pl[1]);
                split2(make_float2(s[2*sk+1][0], s[2*sk+1][1]), ph[2], pl[2]);
                split2(make_float2(s[2*sk+1][2], s[2*sk+1][3]), ph[3], pl[3]);
#pragma unroll
                for (int nb = 0; nb < 4; nb++) {
                    uint32_t vh4[4], vl4[4];
                    ldsm4t(vh4, vhB + (uint32_t)((sk*16*72 + nb*16) * 2));
                    ldsm4t(vl4, vlB + (uint32_t)((sk*16*72 + nb*16) * 2));
                    mma16816(o[2*nb],   ph, vh4);
                    mma16816(o[2*nb+1], ph, vh4 + 2);
                    mma16816(o[2*nb],   ph, vl4);
                    mma16816(o[2*nb+1], ph, vl4 + 2);
                    mma16816(o[2*nb],   pl, vh4);
                    mma16816(o[2*nb+1], pl, vh4 + 2);
                }
            }
        }

        if (kt + 1 < nkt) STORE_KV((kt + 1) & 1);
    }

    {
        float i0 = 1.f / l0, i1 = 1.f / l1;
        __nv_bfloat16* base0 = gHs + (size_t)(b*SS + rloc0) * 1024;
        __nv_bfloat16* base1 = gHs + (size_t)(b*SS + rloc1) * 1024;
#pragma unroll
        for (int nf = 0; nf < 8; nf++) {
            int col = h*64 + nf*8 + 2*tig;
            uint32_t hi, lo;
            split2(make_float2(o[nf][0]*i0, o[nf][1]*i0), hi, lo);
            *(uint32_t*)&base0[col]       = hi;
            *(uint32_t*)&base0[512 + col] = lo;
            split2(make_float2(o[nf][2]*i1, o[nf][3]*i1), hi, lo);
            *(uint32_t*)&base1[col]       = hi;
            *(uint32_t*)&base1[512 + col] = lo;
        }
    }
#undef FETCH_KV
#undef STORE_KV
}

// ---------------------------------------------------------------------------
extern "C" void kernel_launch(void* const* d_in, const int* in_sizes, int n_in,
                              void* d_out, int out_size)
{
    const float* xs  = (const float*)d_in[0];
    const float* xt  = (const float*)d_in[1];
    const float* Wqs = (const float*)d_in[2];
    const float* Wks = (const float*)d_in[3];
    const float* Wvs = (const float*)d_in[4];
    const float* Wvt = (const float*)d_in[7];
    const float* Wqt = (const float*)d_in[5];
    const float* Wkt = (const float*)d_in[6];
    const float* WKb = (const float*)d_in[8];
    const float* Wo  = (const float*)d_in[9];
    float* out = (float*)d_out;

    const int GEMM_SMEM = 3 * 32768;                       // 98304
    const int ATTN_SMEM = 2 * ATTN_BUF * (int)sizeof(__nv_bfloat16);  // 73728
    cudaFuncSetAttribute(mma_gemm, cudaFuncAttributeMaxDynamicSharedMemorySize, GEMM_SMEM);
    cudaFuncSetAttribute(attn_mma, cudaFuncAttributeMaxDynamicSharedMemorySize, ATTN_SMEM);

    prep_A<<<MROWS, 512>>>(xs, xt);
    prep_W<<<(3*512*3072)/256, 256>>>(Wqs, Wks, Wvs, Wqt, Wkt, Wvt);
    prep_Wo<<<(512*1536)/256, 256>>>(Wo);

    mma_gemm<<<dim3(4, 64, 3), 256, GEMM_SMEM>>>(0, nullptr, WKb);
    attn_mma<<<512, 256, ATTN_SMEM>>>();
    mma_gemm<<<dim3(4, 64, 1), 256, GEMM_SMEM>>>(1, out, WKb);
}

// round 6
// speedup vs baseline: 2.9690x; 1.0590x over previous
#include <cuda_runtime.h>
#include <cuda_bf16.h>
#include <cstdint>

#define BB 8
#define SS 1024
#define DD 512
#define NHEADS 8
#define DHEAD 64
#define MROWS (BB*SS)   // 8192

// ---------------- scratch (no allocation allowed) ----------------
// Q/K/V bf16 split planes: [Qh|Ql|Kh|Kl|Vh|Vl], each [B*H][S][64] = 4194304 elems
#define PLANE ((size_t)4194304)
__device__ __nv_bfloat16 gP[6*PLANE];
__device__ __nv_bfloat16 gA[(size_t)MROWS*2048];         // [xs_h | xt_h | xs_l | xt_l]
__device__ __nv_bfloat16 gHs[(size_t)MROWS*1024];        // [H_h | H_l]
__device__ __nv_bfloat16 gBt[(size_t)3*512*3072];        // per-z W_big^T  [n][k]
__device__ __nv_bfloat16 gWoT[(size_t)512*1536];         // Wo_big^T [n][k]

// ---------------- warp-mma helpers ----------------
__device__ __forceinline__ void ldsm4(uint32_t* r, uint32_t addr)
{
    asm volatile("ldmatrix.sync.aligned.m8n8.x4.shared.b16 {%0,%1,%2,%3}, [%4];"
        : "=r"(r[0]), "=r"(r[1]), "=r"(r[2]), "=r"(r[3]) : "r"(addr));
}

__device__ __forceinline__ void ldsm4t(uint32_t* r, uint32_t addr)
{
    asm volatile("ldmatrix.sync.aligned.m8n8.x4.trans.shared.b16 {%0,%1,%2,%3}, [%4];"
        : "=r"(r[0]), "=r"(r[1]), "=r"(r[2]), "=r"(r[3]) : "r"(addr));
}

__device__ __forceinline__ void mma16816(float* c, const uint32_t* a, const uint32_t* b)
{
    asm volatile(
        "mma.sync.aligned.m16n8k16.row.col.f32.bf16.bf16.f32 "
        "{%0,%1,%2,%3}, {%4,%5,%6,%7}, {%8,%9}, {%0,%1,%2,%3};"
        : "+f"(c[0]), "+f"(c[1]), "+f"(c[2]), "+f"(c[3])
        : "r"(a[0]), "r"(a[1]), "r"(a[2]), "r"(a[3]), "r"(b[0]), "r"(b[1]));
}

__device__ __forceinline__ void split2(float2 v, uint32_t& hi, uint32_t& lo)
{
    __nv_bfloat16 hx = __float2bfloat16(v.x);
    __nv_bfloat16 hy = __float2bfloat16(v.y);
    float rx = v.x - __bfloat162float(hx);
    float ry = v.y - __bfloat162float(hy);
    hi = ((uint32_t)__bfloat16_as_ushort(hy) << 16) | (uint32_t)__bfloat16_as_ushort(hx);
    lo = ((uint32_t)__bfloat16_as_ushort(__float2bfloat16(ry)) << 16)
       | (uint32_t)__bfloat16_as_ushort(__float2bfloat16(rx));
}

// ---------------------------------------------------------------------------
// prep kernels
// ---------------------------------------------------------------------------
__global__ void prep_A(const float* __restrict__ xs, const float* __restrict__ xt)
{
    int r = blockIdx.x;
    int c = threadIdx.x;
    float a = xs[(size_t)r*DD + c];
    float b = xt[(size_t)r*DD + c];
    __nv_bfloat16 ah = __float2bfloat16(a);
    __nv_bfloat16 bh = __float2bfloat16(b);
    __nv_bfloat16* row = gA + (size_t)r*2048;
    row[c]        = ah;
    row[512 + c]  = bh;
    row[1024 + c] = __float2bfloat16(a - __bfloat162float(ah));
    row[1536 + c] = __float2bfloat16(b - __bfloat162float(bh));
}

__global__ void prep_W(const float* __restrict__ Wqs, const float* __restrict__ Wks,
                       const float* __restrict__ Wvs, const float* __restrict__ Wqt,
                       const float* __restrict__ Wkt, const float* __restrict__ Wvt)
{
    int idx = blockIdx.x * 256 + threadIdx.x;
    int z   = idx / (512*3072);
    int rem = idx % (512*3072);
    int n   = rem / 3072;
    int k   = rem % 3072;
    const float* W1 = (z==0) ? Wqs : ((z==1) ? Wks : Wvs);
    const float* W2 = (z==0) ? Wqt : ((z==1) ? Wkt : Wvt);
    int kh = k >> 9, ks = k & 511;
    const float* M = (kh & 1) ? W2 : W1;
    float x = M[(size_t)ks*DD + n];
    __nv_bfloat16 v;
    if (kh < 4) v = __float2bfloat16(x);
    else {
        __nv_bfloat16 h = __float2bfloat16(x);
        v = __float2bfloat16(x - __bfloat162float(h));
    }
    gBt[idx] = v;
}

__global__ void prep_Wo(const float* __restrict__ Wo)
{
    int idx = blockIdx.x * 256 + threadIdx.x;
    int n = idx / 1536;
    int k = idx % 1536;
    int kh = k >> 9, ks = k & 511;
    float x = Wo[(size_t)ks*DD + n];
    __nv_bfloat16 v;
    if (kh < 2) v = __float2bfloat16(x);
    else {
        __nv_bfloat16 h = __float2bfloat16(x);
        v = __float2bfloat16(x - __bfloat162float(h));
    }
    gWoT[idx] = v;
}

// ---------------------------------------------------------------------------
// bf16 mma.sync GEMM, 3-stage cp.async pipeline, SW128 swizzle, 1 sync/chunk.
// mode 0: QKV -> bf16 hi/lo planes gP (Q scaled 0.125, K bias-folded)
// mode 1: OUT -> fp32 outp
// ---------------------------------------------------------------------------
__global__ __launch_bounds__(256)
void mma_gemm(int mode, float* __restrict__ outp, const float* __restrict__ WKb)
{
    extern __shared__ __nv_bfloat16 smg[];

    const __nv_bfloat16* A;
    const __nv_bfloat16* Bt;
    int aW, remapC, kEff, nChunks;
    const int z = blockIdx.z;
    if (mode == 0) {
        A = gA; aW = 2048; remapC = 32; kEff = 3072; nChunks = 48;
        Bt = gBt + (size_t)z * 512 * 3072;
    } else {
        A = gHs; aW = 1024; remapC = 16; kEff = 1536; nChunks = 24;
        Bt = gWoT;
    }

    const int mBase = blockIdx.y * 128;
    const int nBase = blockIdx.x * 128;
    const int t    = threadIdx.x;
    const int warp = t >> 5;
    const int lane = t & 31;
    const int wm   = warp >> 2;
    const int wn   = warp & 3;

    const uint32_t sBase = (uint32_t)__cvta_generic_to_shared(smg);

    const int ldRow = t >> 3;
    const int ldSeg = t & 7;
    const uint32_t ldSw = ((uint32_t)ldRow << 7)
                        + (((uint32_t)ldSeg << 4) ^ (((uint32_t)ldRow & 7) << 4));

    float acc[4][4][4];
#pragma unroll
    for (int i = 0; i < 4; i++)
#pragma unroll
        for (int j = 0; j < 4; j++)
#pragma unroll
            for (int q = 0; q < 4; q++) acc[i][j][q] = 0.f;

#define LOAD_CHUNK(cc, buf) do { \
    int acol_ = (((cc) < remapC) ? (cc) : ((cc) - remapC)) << 6; \
    const __nv_bfloat16* Ag_ = A + (size_t)(mBase + ldRow) * aW + acol_ + ldSeg * 8; \
    const __nv_bfloat16* Bg_ = Bt + (size_t)(nBase + ldRow) * kEff + (size_t)(cc) * 64 + ldSeg * 8; \
    uint32_t da_ = sBase + (buf)*32768u + ldSw; \
    uint32_t db_ = da_ + 16384u; \
    _Pragma("unroll") \
    for (int rr_ = 0; rr_ < 4; rr_++) { \
        asm volatile("cp.async.cg.shared.global [%0], [%1], 16;" \
            :: "r"(da_ + rr_*4096u), "l"(__cvta_generic_to_global((const void*)(Ag_ + (size_t)rr_*32*aW)))); \
        asm volatile("cp.async.cg.shared.global [%0], [%1], 16;" \
            :: "r"(db_ + rr_*4096u), "l"(__cvta_generic_to_global((const void*)(Bg_ + (size_t)rr_*32*kEff)))); \
    } \
    asm volatile("cp.async.commit_group;" ::: "memory"); \
} while (0)

    LOAD_CHUNK(0, 0);
    LOAD_CHUNK(1, 1);

    const int aRowL = wm*64 + (lane & 15);
    const int aColB = (((lane >> 4) << 3)) * 2;
    const uint32_t aSw = ((uint32_t)aRowL & 7) << 4;
    const int bRowL = wn*32 + ((lane >> 4) << 3) + (lane & 7);
    const int bColB = ((((lane >> 3) & 1) << 3)) * 2;
    const uint32_t bSw = ((uint32_t)bRowL & 7) << 4;

    for (int c = 0; c < nChunks; c++) {
        const int buf = c % 3;
        if (c + 1 < nChunks) { asm volatile("cp.async.wait_group 1;" ::: "memory"); }
        else                 { asm volatile("cp.async.wait_group 0;" ::: "memory"); }
        __syncthreads();
        if (c + 2 < nChunks) LOAD_CHUNK(c + 2, (c + 2) % 3);

        const uint32_t aB = sBase + buf*32768u;
        const uint32_t bB = aB + 16384u;
#pragma unroll
        for (int ks = 0; ks < 4; ks++) {
            const uint32_t kb = (uint32_t)(ks << 5);
            uint32_t afr[4][4];
#pragma unroll
            for (int mf = 0; mf < 4; mf++)
                ldsm4(afr[mf], aB + (uint32_t)((aRowL + mf*16) << 7) + ((kb + aColB) ^ aSw));
            uint32_t bfr[4][2];
#pragma unroll
            for (int nfp = 0; nfp < 2; nfp++) {
                uint32_t r4[4];
                ldsm4(r4, bB + (uint32_t)((bRowL + nfp*16) << 7) + ((kb + bColB) ^ bSw));
                bfr[nfp*2+0][0] = r4[0]; bfr[nfp*2+0][1] = r4[1];
                bfr[nfp*2+1][0] = r4[2]; bfr[nfp*2+1][1] = r4[3];
            }
#pragma unroll
            for (int mf = 0; mf < 4; mf++)
#pragma unroll
                for (int nf = 0; nf < 4; nf++)
                    mma16816(acc[mf][nf], afr[mf], bfr[nf]);
        }
    }

    const int g   = lane >> 2;
    const int tig = lane & 3;

    if (mode == 0) {
        __nv_bfloat16* Ph = gP + (size_t)(2*z) * PLANE;
        __nv_bfloat16* Pl = Ph + PLANE;
#pragma unroll
        for (int mf = 0; mf < 4; mf++) {
            int row0 = mBase + wm*64 + mf*16 + g;
            int bb = row0 >> 10, s0 = row0 & (SS-1);
#pragma unroll
            for (int nf = 0; nf < 4; nf++) {
                int col = nBase + wn*32 + nf*8 + tig*2;
                int hh = col >> 6, d = col & 63;
                float c0 = acc[mf][nf][0], c1 = acc[mf][nf][1];
                float c2 = acc[mf][nf][2], c3 = acc[mf][nf][3];
                if (z == 0) { c0 *= 0.125f; c1 *= 0.125f; c2 *= 0.125f; c3 *= 0.125f; }
                else if (z == 1) {
                    c0 += WKb[d*SS + s0];       c1 += WKb[(d+1)*SS + s0];
                    c2 += WKb[d*SS + s0 + 8];   c3 += WKb[(d+1)*SS + s0 + 8];
                }
                size_t off0 = ((size_t)(bb*NHEADS + hh)*SS + s0)*64 + d;
                uint32_t hi, lo;
                split2(make_float2(c0, c1), hi, lo);
                *(uint32_t*)&Ph[off0] = hi;
                *(uint32_t*)&Pl[off0] = lo;
                split2(make_float2(c2, c3), hi, lo);
                *(uint32_t*)&Ph[off0 + 512] = hi;      // row0+8 -> +8*64
                *(uint32_t*)&Pl[off0 + 512] = lo;
            }
        }
    } else {
#pragma unroll
        for (int mf = 0; mf < 4; mf++) {
            int row0 = mBase + wm*64 + mf*16 + g;
#pragma unroll
            for (int nf = 0; nf < 4; nf++) {
                int col = nBase + wn*32 + nf*8 + tig*2;
                *(float2*)&outp[(size_t)row0*DD + col]
                    = make_float2(acc[mf][nf][0], acc[mf][nf][1]);
                *(float2*)&outp[(size_t)(row0+8)*DD + col]
                    = make_float2(acc[mf][nf][2], acc[mf][nf][3]);
            }
        }
    }
#undef LOAD_CHUNK
}

// ---------------------------------------------------------------------------
// tensor-core causal flash attention: pure bf16 planes, cp.async double-buffer,
// swizzled smem, one __syncthreads per K-tile, no in-loop conversion.
// smem buffer (32KB): [Kh 8K | Kl 8K | Vh 8K | Vl 8K], 2 buffers.
// ---------------------------------------------------------------------------
__global__ __launch_bounds__(256, 1) void attn_mma()
{
    extern __shared__ __nv_bfloat16 sma[];

    const int bx = blockIdx.x;
    const int qt = 7 - (bx >> 6);
    const int bh = bx & 63;
    const int b = bh >> 3, h = bh & 7;
    const int t = threadIdx.x, warp = t >> 5, lane = t & 31;
    const int g = lane >> 2, tig = lane & 3;

    const size_t bhOff = (size_t)(b*NHEADS + h) * SS * 64;
    const __nv_bfloat16* pQh = gP + bhOff;
    const __nv_bfloat16* pQl = gP + PLANE   + bhOff;
    const __nv_bfloat16* pKh = gP + 2*PLANE + bhOff;
    const __nv_bfloat16* pKl = gP + 3*PLANE + bhOff;
    const __nv_bfloat16* pVh = gP + 4*PLANE + bhOff;
    const __nv_bfloat16* pVl = gP + 5*PLANE + bhOff;

    const int rloc0 = qt*128 + warp*16 + g;
    const int rloc1 = rloc0 + 8;

    // ---- Q fragments: direct packed loads (already scaled & split)
    uint32_t qh[4][4], ql[4][4];
    {
        const size_t q0 = (size_t)rloc0 * 64 + 2*tig;
        const size_t q1 = (size_t)rloc1 * 64 + 2*tig;
#pragma unroll
        for (int s = 0; s < 4; s++) {
            qh[s][0] = *(const uint32_t*)&pQh[q0 + s*16];
            qh[s][1] = *(const uint32_t*)&pQh[q1 + s*16];
            qh[s][2] = *(const uint32_t*)&pQh[q0 + s*16 + 8];
            qh[s][3] = *(const uint32_t*)&pQh[q1 + s*16 + 8];
            ql[s][0] = *(const uint32_t*)&pQl[q0 + s*16];
            ql[s][1] = *(const uint32_t*)&pQl[q1 + s*16];
            ql[s][2] = *(const uint32_t*)&pQl[q0 + s*16 + 8];
            ql[s][3] = *(const uint32_t*)&pQl[q1 + s*16 + 8];
        }
    }

    float o[8][4];
#pragma unroll
    for (int nf = 0; nf < 8; nf++)
#pragma unroll
        for (int j = 0; j < 4; j++) o[nf][j] = 0.f;
    float m0 = -1e30f, m1 = -1e30f, l0 = 0.f, l1 = 0.f;

    const uint32_t smB = (uint32_t)__cvta_generic_to_shared(sma);
    const int lr8 = t >> 2;            // 0..63 row
    const int ls  = t & 3;             // 2 segments each
    const uint32_t swst = ((uint32_t)lr8 & 7) << 4;

#define LOAD_TILE(kt_, buf_) do { \
    const size_t ro_ = (size_t)((kt_)*64 + lr8) * 64; \
    uint32_t db_ = smB + (uint32_t)((buf_)*32768) + (uint32_t)(lr8*128); \
    _Pragma("unroll") \
    for (int sg_ = 0; sg_ < 2; sg_++) { \
        int seg_ = ls*2 + sg_; \
        uint32_t co_ = ((uint32_t)(seg_*16)) ^ swst; \
        asm volatile("cp.async.cg.shared.global [%0], [%1], 16;" \
            :: "r"(db_ + co_),          "l"(__cvta_generic_to_global((const void*)(pKh + ro_ + seg_*8)))); \
        asm volatile("cp.async.cg.shared.global [%0], [%1], 16;" \
            :: "r"(db_ + 8192u + co_),  "l"(__cvta_generic_to_global((const void*)(pKl + ro_ + seg_*8)))); \
        asm volatile("cp.async.cg.shared.global [%0], [%1], 16;" \
            :: "r"(db_ + 16384u + co_), "l"(__cvta_generic_to_global((const void*)(pVh + ro_ + seg_*8)))); \
        asm volatile("cp.async.cg.shared.global [%0], [%1], 16;" \
            :: "r"(db_ + 24576u + co_), "l"(__cvta_generic_to_global((const void*)(pVl + ro_ + seg_*8)))); \
    } \
    asm volatile("cp.async.commit_group;" ::: "memory"); \
} while (0)

    // ldmatrix geometry
    const uint32_t swf = (uint32_t)(lane & 7) << 4;
    const uint32_t kRowB = (uint32_t)((((lane>>4)<<3) | (lane&7)) * 128);
    const uint32_t kColS = (uint32_t)(((lane>>3)&1) << 4);
    const uint32_t vRowB = (uint32_t)((lane & 15) * 128);
    const uint32_t vColS = (uint32_t)((lane>>4) << 4);

    const int nkt = 2*qt + 2;
    LOAD_TILE(0, 0);

    for (int kt = 0; kt < nkt; kt++) {
        asm volatile("cp.async.wait_group 0;" ::: "memory");
        __syncthreads();
        if (kt + 1 < nkt) LOAD_TILE(kt + 1, (kt + 1) & 1);

        const uint32_t bufB = smB + (uint32_t)((kt & 1) * 32768);
        const bool active = (qt*128 + warp*16 + 15) >= kt*64;
        if (active) {
            float s[8][4];
#pragma unroll
            for (int nf = 0; nf < 8; nf++)
#pragma unroll
                for (int j = 0; j < 4; j++) s[nf][j] = 0.f;

#pragma unroll
            for (int nfp = 0; nfp < 4; nfp++) {
                const uint32_t rowOff = bufB + kRowB + (uint32_t)(nfp*2048);
#pragma unroll
                for (int ks = 0; ks < 4; ks++) {
                    uint32_t kr[4];
                    ldsm4(kr, rowOff + (((uint32_t)(ks*32) + kColS) ^ swf));
                    mma16816(s[2*nfp],   qh[ks], kr);
                    mma16816(s[2*nfp+1], qh[ks], kr + 2);
                    mma16816(s[2*nfp],   ql[ks], kr);
                    mma16816(s[2*nfp+1], ql[ks], kr + 2);
                    ldsm4(kr, rowOff + 8192u + (((uint32_t)(ks*32) + kColS) ^ swf));
                    mma16816(s[2*nfp],   qh[ks], kr);
                    mma16816(s[2*nfp+1], qh[ks], kr + 2);
                }
            }

            if (kt >= 2*qt) {
                const int key0 = kt*64;
#pragma unroll
                for (int nf = 0; nf < 8; nf++) {
                    int kc = key0 + nf*8 + 2*tig;
                    if (kc     > rloc0) s[nf][0] = -1e30f;
                    if (kc + 1 > rloc0) s[nf][1] = -1e30f;
                    if (kc     > rloc1) s[nf][2] = -1e30f;
                    if (kc + 1 > rloc1) s[nf][3] = -1e30f;
                }
            }

            float mx0 = -1e30f, mx1 = -1e30f;
#pragma unroll
            for (int nf = 0; nf < 8; nf++) {
                mx0 = fmaxf(mx0, fmaxf(s[nf][0], s[nf][1]));
                mx1 = fmaxf(mx1, fmaxf(s[nf][2], s[nf][3]));
            }
            mx0 = fmaxf(mx0, __shfl_xor_sync(0xffffffffu, mx0, 1));
            mx0 = fmaxf(mx0, __shfl_xor_sync(0xffffffffu, mx0, 2));
            mx1 = fmaxf(mx1, __shfl_xor_sync(0xffffffffu, mx1, 1));
            mx1 = fmaxf(mx1, __shfl_xor_sync(0xffffffffu, mx1, 2));
            float mn0 = fmaxf(m0, mx0), mn1 = fmaxf(m1, mx1);
            float a0 = __expf(m0 - mn0), a1 = __expf(m1 - mn1);
            m0 = mn0; m1 = mn1;
            float sum0 = 0.f, sum1 = 0.f;
#pragma unroll
            for (int nf = 0; nf < 8; nf++) {
                s[nf][0] = __expf(s[nf][0] - mn0);
                s[nf][1] = __expf(s[nf][1] - mn0);
                s[nf][2] = __expf(s[nf][2] - mn1);
                s[nf][3] = __expf(s[nf][3] - mn1);
                sum0 += s[nf][0] + s[nf][1];
                sum1 += s[nf][2] + s[nf][3];
            }
            sum0 += __shfl_xor_sync(0xffffffffu, sum0, 1);
            sum0 += __shfl_xor_sync(0xffffffffu, sum0, 2);
            sum1 += __shfl_xor_sync(0xffffffffu, sum1, 1);
            sum1 += __shfl_xor_sync(0xffffffffu, sum1, 2);
            l0 = l0*a0 + sum0;
            l1 = l1*a1 + sum1;
#pragma unroll
            for (int nf = 0; nf < 8; nf++) {
                o[nf][0] *= a0; o[nf][1] *= a0;
                o[nf][2] *= a1; o[nf][3] *= a1;
            }

#pragma unroll
            for (int sk = 0; sk < 4; sk++) {
                uint32_t ph[4], pl[4];
                split2(make_float2(s[2*sk][0],   s[2*sk][1]),   ph[0], pl[0]);
                split2(make_float2(s[2*sk][2],   s[2*sk][3]),   ph[1], pl[1]);
                split2(make_float2(s[2*sk+1][0], s[2*sk+1][1]), ph[2], pl[2]);
                split2(make_float2(s[2*sk+1][2], s[2*sk+1][3]), ph[3], pl[3]);
                const uint32_t vOff = bufB + 16384u + vRowB + (uint32_t)(sk*2048);
#pragma unroll
                for (int nb = 0; nb < 4; nb++) {
                    uint32_t vh4[4], vl4[4];
                    uint32_t co = (((uint32_t)(nb*32) + vColS) ^ swf);
                    ldsm4t(vh4, vOff + co);
                    ldsm4t(vl4, vOff + 8192u + co);
                    mma16816(o[2*nb],   ph, vh4);
                    mma16816(o[2*nb+1], ph, vh4 + 2);
                    mma16816(o[2*nb],   ph, vl4);
                    mma16816(o[2*nb+1], ph, vl4 + 2);
                    mma16816(o[2*nb],   pl, vh4);
                    mma16816(o[2*nb+1], pl, vh4 + 2);
                }
            }
        }
    }

    {
        float i0 = 1.f / l0, i1 = 1.f / l1;
        __nv_bfloat16* base0 = gHs + (size_t)(b*SS + rloc0) * 1024;
        __nv_bfloat16* base1 = gHs + (size_t)(b*SS + rloc1) * 1024;
#pragma unroll
        for (int nf = 0; nf < 8; nf++) {
            int col = h*64 + nf*8 + 2*tig;
            uint32_t hi, lo;
            split2(make_float2(o[nf][0]*i0, o[nf][1]*i0), hi, lo);
            *(uint32_t*)&base0[col]       = hi;
            *(uint32_t*)&base0[512 + col] = lo;
            split2(make_float2(o[nf][2]*i1, o[nf][3]*i1), hi, lo);
            *(uint32_t*)&base1[col]       = hi;
            *(uint32_t*)&base1[512 + col] = lo;
        }
    }
#undef LOAD_TILE
}

// ---------------------------------------------------------------------------
extern "C" void kernel_launch(void* const* d_in, const int* in_sizes, int n_in,
                              void* d_out, int out_size)
{
    const float* xs  = (const float*)d_in[0];
    const float* xt  = (const float*)d_in[1];
    const float* Wqs = (const float*)d_in[2];
    const float* Wks = (const float*)d_in[3];
    const float* Wvs = (const float*)d_in[4];
    const float* Wqt = (const float*)d_in[5];
    const float* Wkt = (const float*)d_in[6];
    const float* Wvt = (const float*)d_in[7];
    const float* WKb = (const float*)d_in[8];
    const float* Wo  = (const float*)d_in[9];
    float* out = (float*)d_out;

    const int GEMM_SMEM = 3 * 32768;      // 98304
    const int ATTN_SMEM = 2 * 32768;      // 65536
    cudaFuncSetAttribute(mma_gemm, cudaFuncAttributeMaxDynamicSharedMemorySize, GEMM_SMEM);
    cudaFuncSetAttribute(attn_mma, cudaFuncAttributeMaxDynamicSharedMemorySize, ATTN_SMEM);

    prep_A<<<MROWS, 512>>>(xs, xt);
    prep_W<<<(3*512*3072)/256, 256>>>(Wqs, Wks, Wvs, Wqt, Wkt, Wvt);
    prep_Wo<<<(512*1536)/256, 256>>>(Wo);

    mma_gemm<<<dim3(4, 64, 3), 256, GEMM_SMEM>>>(0, nullptr, WKb);
    attn_mma<<<512, 256, ATTN_SMEM>>>();
    mma_gemm<<<dim3(4, 64, 1), 256, GEMM_SMEM>>>(1, out, WKb);
}

// round 7
// speedup vs baseline: 3.9993x; 1.3470x over previous
#include <cuda_runtime.h>
#include <cuda_fp16.h>
#include <cstdint>

#define BB 8
#define SS 1024
#define DD 512
#define NHEADS 8
#define DHEAD 64
#define MROWS (BB*SS)   // 8192

// ---------------- scratch (no allocation allowed) ----------------
// fp16 split planes: [Qh|Ql|Kh|Kl|Vh], each [B*H][S][64] = 4194304 elems
#define PLANE ((size_t)4194304)
__device__ __half gP[5*PLANE];
__device__ __half gA[(size_t)MROWS*2048];       // [xs_h | xt_h | xs_l | xt_l]
__device__ __half gHs[(size_t)MROWS*1024];      // [H_h | H_l]
__device__ __half gBt[(size_t)3*512*2048];      // per-z W^T k-blocks [W1h,W2h,W1h,W2h]
__device__ __half gWoT[(size_t)512*1024];       // Wo^T k-blocks [Woh,Woh]

// ---------------- warp-mma helpers ----------------
__device__ __forceinline__ void ldsm4(uint32_t* r, uint32_t addr)
{
    asm volatile("ldmatrix.sync.aligned.m8n8.x4.shared.b16 {%0,%1,%2,%3}, [%4];"
        : "=r"(r[0]), "=r"(r[1]), "=r"(r[2]), "=r"(r[3]) : "r"(addr));
}

__device__ __forceinline__ void ldsm4t(uint32_t* r, uint32_t addr)
{
    asm volatile("ldmatrix.sync.aligned.m8n8.x4.trans.shared.b16 {%0,%1,%2,%3}, [%4];"
        : "=r"(r[0]), "=r"(r[1]), "=r"(r[2]), "=r"(r[3]) : "r"(addr));
}

__device__ __forceinline__ void mma16816(float* c, const uint32_t* a, const uint32_t* b)
{
    asm volatile(
        "mma.sync.aligned.m16n8k16.row.col.f32.f16.f16.f32 "
        "{%0,%1,%2,%3}, {%4,%5,%6,%7}, {%8,%9}, {%0,%1,%2,%3};"
        : "+f"(c[0]), "+f"(c[1]), "+f"(c[2]), "+f"(c[3])
        : "r"(a[0]), "r"(a[1]), "r"(a[2]), "r"(a[3]), "r"(b[0]), "r"(b[1]));
}

// split a float2 into packed fp16 hi pair + fp16 residual pair
__device__ __forceinline__ void split2(float2 v, uint32_t& hi, uint32_t& lo)
{
    __half hx = __float2half_rn(v.x);
    __half hy = __float2half_rn(v.y);
    float rx = v.x - __half2float(hx);
    float ry = v.y - __half2float(hy);
    hi = ((uint32_t)__half_as_ushort(hy) << 16) | (uint32_t)__half_as_ushort(hx);
    lo = ((uint32_t)__half_as_ushort(__float2half_rn(ry)) << 16)
       | (uint32_t)__half_as_ushort(__float2half_rn(rx));
}

// ---------------------------------------------------------------------------
// prep kernels
// ---------------------------------------------------------------------------
__global__ void prep_A(const float* __restrict__ xs, const float* __restrict__ xt)
{
    int r = blockIdx.x;
    int c = threadIdx.x;
    float a = xs[(size_t)r*DD + c];
    float b = xt[(size_t)r*DD + c];
    __half ah = __float2half_rn(a);
    __half bh = __float2half_rn(b);
    __half* row = gA + (size_t)r*2048;
    row[c]        = ah;
    row[512 + c]  = bh;
    row[1024 + c] = __float2half_rn(a - __half2float(ah));
    row[1536 + c] = __float2half_rn(b - __half2float(bh));
}

// gBt[z][n][k], K=2048, k-blocks: [W1h, W2h, W1h, W2h]
__global__ void prep_W(const float* __restrict__ Wqs, const float* __restrict__ Wks,
                       const float* __restrict__ Wvs, const float* __restrict__ Wqt,
                       const float* __restrict__ Wkt, const float* __restrict__ Wvt)
{
    int idx = blockIdx.x * 256 + threadIdx.x;      // 3*512*2048
    int z   = idx / (512*2048);
    int rem = idx % (512*2048);
    int n   = rem / 2048;
    int k   = rem % 2048;
    const float* W1 = (z==0) ? Wqs : ((z==1) ? Wks : Wvs);
    const float* W2 = (z==0) ? Wqt : ((z==1) ? Wkt : Wvt);
    int kh = k >> 9, ks = k & 511;
    const float* M = (kh & 1) ? W2 : W1;
    gBt[idx] = __float2half_rn(M[(size_t)ks*DD + n]);
}

// gWoT[n][k], K=1024, k-blocks: [Woh, Woh]
__global__ void prep_Wo(const float* __restrict__ Wo)
{
    int idx = blockIdx.x * 256 + threadIdx.x;      // 512*1024
    int n = idx / 1024;
    int k = idx % 1024;
    int ks = k & 511;
    gWoT[idx] = __float2half_rn(Wo[(size_t)ks*DD + n]);
}

// ---------------------------------------------------------------------------
// fp16 mma.sync GEMM, 3-stage cp.async pipeline, SW128 swizzle, 1 sync/chunk.
// mode 0: QKV -> fp16 hi/lo planes gP (Q scaled 0.125, K bias-folded, V hi only)
// mode 1: OUT -> fp32 outp
// ---------------------------------------------------------------------------
__global__ __launch_bounds__(256)
void mma_gemm(int mode, float* __restrict__ outp, const float* __restrict__ WKb)
{
    extern __shared__ __half smg[];

    const __half* A;
    const __half* Bt;
    int aW, kEff, nChunks;
    const int z = blockIdx.z;
    if (mode == 0) {
        A = gA; aW = 2048; kEff = 2048; nChunks = 32;
        Bt = gBt + (size_t)z * 512 * 2048;
    } else {
        A = gHs; aW = 1024; kEff = 1024; nChunks = 16;
        Bt = gWoT;
    }

    const int mBase = blockIdx.y * 128;
    const int nBase = blockIdx.x * 128;
    const int t    = threadIdx.x;
    const int warp = t >> 5;
    const int lane = t & 31;
    const int wm   = warp >> 2;
    const int wn   = warp & 3;

    const uint32_t sBase = (uint32_t)__cvta_generic_to_shared(smg);

    const int ldRow = t >> 3;
    const int ldSeg = t & 7;
    const uint32_t ldSw = ((uint32_t)ldRow << 7)
                        + (((uint32_t)ldSeg << 4) ^ (((uint32_t)ldRow & 7) << 4));

    float acc[4][4][4];
#pragma unroll
    for (int i = 0; i < 4; i++)
#pragma unroll
        for (int j = 0; j < 4; j++)
#pragma unroll
            for (int q = 0; q < 4; q++) acc[i][j][q] = 0.f;

#define LOAD_CHUNK(cc, buf) do { \
    const __half* Ag_ = A + (size_t)(mBase + ldRow) * aW + ((cc) << 6) + ldSeg * 8; \
    const __half* Bg_ = Bt + (size_t)(nBase + ldRow) * kEff + (size_t)(cc) * 64 + ldSeg * 8; \
    uint32_t da_ = sBase + (buf)*32768u + ldSw; \
    uint32_t db_ = da_ + 16384u; \
    _Pragma("unroll") \
    for (int rr_ = 0; rr_ < 4; rr_++) { \
        asm volatile("cp.async.cg.shared.global [%0], [%1], 16;" \
            :: "r"(da_ + rr_*4096u), "l"(__cvta_generic_to_global((const void*)(Ag_ + (size_t)rr_*32*aW)))); \
        asm volatile("cp.async.cg.shared.global [%0], [%1], 16;" \
            :: "r"(db_ + rr_*4096u), "l"(__cvta_generic_to_global((const void*)(Bg_ + (size_t)rr_*32*kEff)))); \
    } \
    asm volatile("cp.async.commit_group;" ::: "memory"); \
} while (0)

    LOAD_CHUNK(0, 0);
    LOAD_CHUNK(1, 1);

    const int aRowL = wm*64 + (lane & 15);
    const int aColB = (((lane >> 4) << 3)) * 2;
    const uint32_t aSw = ((uint32_t)aRowL & 7) << 4;
    const int bRowL = wn*32 + ((lane >> 4) << 3) + (lane & 7);
    const int bColB = ((((lane >> 3) & 1) << 3)) * 2;
    const uint32_t bSw = ((uint32_t)bRowL & 7) << 4;

    for (int c = 0; c < nChunks; c++) {
        const int buf = c % 3;
        if (c + 1 < nChunks) { asm volatile("cp.async.wait_group 1;" ::: "memory"); }
        else                 { asm volatile("cp.async.wait_group 0;" ::: "memory"); }
        __syncthreads();
        if (c + 2 < nChunks) LOAD_CHUNK(c + 2, (c + 2) % 3);

        const uint32_t aB = sBase + buf*32768u;
        const uint32_t bB = aB + 16384u;
#pragma unroll
        for (int ks = 0; ks < 4; ks++) {
            const uint32_t kb = (uint32_t)(ks << 5);
            uint32_t afr[4][4];
#pragma unroll
            for (int mf = 0; mf < 4; mf++)
                ldsm4(afr[mf], aB + (uint32_t)((aRowL + mf*16) << 7) + ((kb + aColB) ^ aSw));
            uint32_t bfr[4][2];
#pragma unroll
            for (int nfp = 0; nfp < 2; nfp++) {
                uint32_t r4[4];
                ldsm4(r4, bB + (uint32_t)((bRowL + nfp*16) << 7) + ((kb + bColB) ^ bSw));
                bfr[nfp*2+0][0] = r4[0]; bfr[nfp*2+0][1] = r4[1];
                bfr[nfp*2+1][0] = r4[2]; bfr[nfp*2+1][1] = r4[3];
            }
#pragma unroll
            for (int mf = 0; mf < 4; mf++)
#pragma unroll
                for (int nf = 0; nf < 4; nf++)
                    mma16816(acc[mf][nf], afr[mf], bfr[nf]);
        }
    }

    const int g   = lane >> 2;
    const int tig = lane & 3;

    if (mode == 0) {
        // planes: Qh=0, Ql=1, Kh=2, Kl=3, Vh=4
        __half* Ph = gP + (size_t)((z==0) ? 0 : (z==1) ? 2 : 4) * PLANE;
        __half* Pl = Ph + PLANE;                         // unused for z==2
#pragma unroll
        for (int mf = 0; mf < 4; mf++) {
            int row0 = mBase + wm*64 + mf*16 + g;
            int bb = row0 >> 10, s0 = row0 & (SS-1);
#pragma unroll
            for (int nf = 0; nf < 4; nf++) {
                int col = nBase + wn*32 + nf*8 + tig*2;
                int hh = col >> 6, d = col & 63;
                float c0 = acc[mf][nf][0], c1 = acc[mf][nf][1];
                float c2 = acc[mf][nf][2], c3 = acc[mf][nf][3];
                if (z == 0) { c0 *= 0.125f; c1 *= 0.125f; c2 *= 0.125f; c3 *= 0.125f; }
                else if (z == 1) {
                    c0 += WKb[d*SS + s0];       c1 += WKb[(d+1)*SS + s0];
                    c2 += WKb[d*SS + s0 + 8];   c3 += WKb[(d+1)*SS + s0 + 8];
                }
                size_t off0 = ((size_t)(bb*NHEADS + hh)*SS + s0)*64 + d;
                uint32_t hi, lo;
                split2(make_float2(c0, c1), hi, lo);
                *(uint32_t*)&Ph[off0] = hi;
                if (z < 2) *(uint32_t*)&Pl[off0] = lo;
                split2(make_float2(c2, c3), hi, lo);
                *(uint32_t*)&Ph[off0 + 512] = hi;
                if (z < 2) *(uint32_t*)&Pl[off0 + 512] = lo;
            }
        }
    } else {
#pragma unroll
        for (int mf = 0; mf < 4; mf++) {
            int row0 = mBase + wm*64 + mf*16 + g;
#pragma unroll
            for (int nf = 0; nf < 4; nf++) {
                int col = nBase + wn*32 + nf*8 + tig*2;
                *(float2*)&outp[(size_t)row0*DD + col]
                    = make_float2(acc[mf][nf][0], acc[mf][nf][1]);
                *(float2*)&outp[(size_t)(row0+8)*DD + col]
                    = make_float2(acc[mf][nf][2], acc[mf][nf][3]);
            }
        }
    }
#undef LOAD_CHUNK
}

// ---------------------------------------------------------------------------
// fp16 tensor-core causal flash attention. Scores 3-term, PV 2-term (Vh only).
// smem buffer (24KB): [Kh 8K | Kl 8K | Vh 8K], 2 buffers, 1 sync/tile.
// ---------------------------------------------------------------------------
__global__ __launch_bounds__(256, 1) void attn_mma()
{
    extern __shared__ __half sma[];

    const int bx = blockIdx.x;
    const int qt = 7 - (bx >> 6);
    const int bh = bx & 63;
    const int b = bh >> 3, h = bh & 7;
    const int t = threadIdx.x, warp = t >> 5, lane = t & 31;
    const int g = lane >> 2, tig = lane & 3;

    const size_t bhOff = (size_t)(b*NHEADS + h) * SS * 64;
    const __half* pQh = gP + bhOff;
    const __half* pQl = gP + PLANE   + bhOff;
    const __half* pKh = gP + 2*PLANE + bhOff;
    const __half* pKl = gP + 3*PLANE + bhOff;
    const __half* pVh = gP + 4*PLANE + bhOff;

    const int rloc0 = qt*128 + warp*16 + g;
    const int rloc1 = rloc0 + 8;

    uint32_t qh[4][4], ql[4][4];
    {
        const size_t q0 = (size_t)rloc0 * 64 + 2*tig;
        const size_t q1 = (size_t)rloc1 * 64 + 2*tig;
#pragma unroll
        for (int s = 0; s < 4; s++) {
            qh[s][0] = *(const uint32_t*)&pQh[q0 + s*16];
            qh[s][1] = *(const uint32_t*)&pQh[q1 + s*16];
            qh[s][2] = *(const uint32_t*)&pQh[q0 + s*16 + 8];
            qh[s][3] = *(const uint32_t*)&pQh[q1 + s*16 + 8];
            ql[s][0] = *(const uint32_t*)&pQl[q0 + s*16];
            ql[s][1] = *(const uint32_t*)&pQl[q1 + s*16];
            ql[s][2] = *(const uint32_t*)&pQl[q0 + s*16 + 8];
            ql[s][3] = *(const uint32_t*)&pQl[q1 + s*16 + 8];
        }
    }

    float o[8][4];
#pragma unroll
    for (int nf = 0; nf < 8; nf++)
#pragma unroll
        for (int j = 0; j < 4; j++) o[nf][j] = 0.f;
    float m0 = -1e30f, m1 = -1e30f, l0 = 0.f, l1 = 0.f;

    const uint32_t smB = (uint32_t)__cvta_generic_to_shared(sma);
    const int lr8 = t >> 2;
    const int ls  = t & 3;
    const uint32_t swst = ((uint32_t)lr8 & 7) << 4;

#define LOAD_TILE(kt_, buf_) do { \
    const size_t ro_ = (size_t)((kt_)*64 + lr8) * 64; \
    uint32_t db_ = smB + (uint32_t)((buf_)*24576) + (uint32_t)(lr8*128); \
    _Pragma("unroll") \
    for (int sg_ = 0; sg_ < 2; sg_++) { \
        int seg_ = ls*2 + sg_; \
        uint32_t co_ = ((uint32_t)(seg_*16)) ^ swst; \
        asm volatile("cp.async.cg.shared.global [%0], [%1], 16;" \
            :: "r"(db_ + co_),          "l"(__cvta_generic_to_global((const void*)(pKh + ro_ + seg_*8)))); \
        asm volatile("cp.async.cg.shared.global [%0], [%1], 16;" \
            :: "r"(db_ + 8192u + co_),  "l"(__cvta_generic_to_global((const void*)(pKl + ro_ + seg_*8)))); \
        asm volatile("cp.async.cg.shared.global [%0], [%1], 16;" \
            :: "r"(db_ + 16384u + co_), "l"(__cvta_generic_to_global((const void*)(pVh + ro_ + seg_*8)))); \
    } \
    asm volatile("cp.async.commit_group;" ::: "memory"); \
} while (0)

    const uint32_t swf = (uint32_t)(lane & 7) << 4;
    const uint32_t kRowB = (uint32_t)((((lane>>4)<<3) | (lane&7)) * 128);
    const uint32_t kColS = (uint32_t)(((lane>>3)&1) << 4);
    const uint32_t vRowB = (uint32_t)((lane & 15) * 128);
    const uint32_t vColS = (uint32_t)((lane>>4) << 4);

    const int nkt = 2*qt + 2;
    LOAD_TILE(0, 0);

    for (int kt = 0; kt < nkt; kt++) {
        asm volatile("cp.async.wait_group 0;" ::: "memory");
        __syncthreads();
        if (kt + 1 < nkt) LOAD_TILE(kt + 1, (kt + 1) & 1);

        const uint32_t bufB = smB + (uint32_t)((kt & 1) * 24576);
        const bool active = (qt*128 + warp*16 + 15) >= kt*64;
        if (active) {
            float s[8][4];
#pragma unroll
            for (int nf = 0; nf < 8; nf++)
#pragma unroll
                for (int j = 0; j < 4; j++) s[nf][j] = 0.f;

#pragma unroll
            for (int nfp = 0; nfp < 4; nfp++) {
                const uint32_t rowOff = bufB + kRowB + (uint32_t)(nfp*2048);
#pragma unroll
                for (int ks = 0; ks < 4; ks++) {
                    uint32_t kr[4];
                    ldsm4(kr, rowOff + (((uint32_t)(ks*32) + kColS) ^ swf));
                    mma16816(s[2*nfp],   qh[ks], kr);
                    mma16816(s[2*nfp+1], qh[ks], kr + 2);
                    mma16816(s[2*nfp],   ql[ks], kr);
                    mma16816(s[2*nfp+1], ql[ks], kr + 2);
                    ldsm4(kr, rowOff + 8192u + (((uint32_t)(ks*32) + kColS) ^ swf));
                    mma16816(s[2*nfp],   qh[ks], kr);
                    mma16816(s[2*nfp+1], qh[ks], kr + 2);
                }
            }

            if (kt >= 2*qt) {
                const int key0 = kt*64;
#pragma unroll
                for (int nf = 0; nf < 8; nf++) {
                    int kc = key0 + nf*8 + 2*tig;
                    if (kc     > rloc0) s[nf][0] = -1e30f;
                    if (kc + 1 > rloc0) s[nf][1] = -1e30f;
                    if (kc     > rloc1) s[nf][2] = -1e30f;
                    if (kc + 1 > rloc1) s[nf][3] = -1e30f;
                }
            }

            float mx0 = -1e30f, mx1 = -1e30f;
#pragma unroll
            for (int nf = 0; nf < 8; nf++) {
                mx0 = fmaxf(mx0, fmaxf(s[nf][0], s[nf][1]));
                mx1 = fmaxf(mx1, fmaxf(s[nf][2], s[nf][3]));
            }
            mx0 = fmaxf(mx0, __shfl_xor_sync(0xffffffffu, mx0, 1));
            mx0 = fmaxf(mx0, __shfl_xor_sync(0xffffffffu, mx0, 2));
            mx1 = fmaxf(mx1, __shfl_xor_sync(0xffffffffu, mx1, 1));
            mx1 = fmaxf(mx1, __shfl_xor_sync(0xffffffffu, mx1, 2));
            float mn0 = fmaxf(m0, mx0), mn1 = fmaxf(m1, mx1);
            float a0 = __expf(m0 - mn0), a1 = __expf(m1 - mn1);
            m0 = mn0; m1 = mn1;
            float sum0 = 0.f, sum1 = 0.f;
#pragma unroll
            for (int nf = 0; nf < 8; nf++) {
                s[nf][0] = __expf(s[nf][0] - mn0);
                s[nf][1] = __expf(s[nf][1] - mn0);
                s[nf][2] = __expf(s[nf][2] - mn1);
                s[nf][3] = __expf(s[nf][3] - mn1);
                sum0 += s[nf][0] + s[nf][1];
                sum1 += s[nf][2] + s[nf][3];
            }
            sum0 += __shfl_xor_sync(0xffffffffu, sum0, 1);
            sum0 += __shfl_xor_sync(0xffffffffu, sum0, 2);
            sum1 += __shfl_xor_sync(0xffffffffu, sum1, 1);
            sum1 += __shfl_xor_sync(0xffffffffu, sum1, 2);
            l0 = l0*a0 + sum0;
            l1 = l1*a1 + sum1;
#pragma unroll
            for (int nf = 0; nf < 8; nf++) {
                o[nf][0] *= a0; o[nf][1] *= a0;
                o[nf][2] *= a1; o[nf][3] *= a1;
            }

            // O += (Ph + Pl) @ Vh
#pragma unroll
            for (int sk = 0; sk < 4; sk++) {
                uint32_t ph[4], pl[4];
                split2(make_float2(s[2*sk][0],   s[2*sk][1]),   ph[0], pl[0]);
                split2(make_float2(s[2*sk][2],   s[2*sk][3]),   ph[1], pl[1]);
                split2(make_float2(s[2*sk+1][0], s[2*sk+1][1]), ph[2], pl[2]);
                split2(make_float2(s[2*sk+1][2], s[2*sk+1][3]), ph[3], pl[3]);
                const uint32_t vOff = bufB + 16384u + vRowB + (uint32_t)(sk*2048);
#pragma unroll
                for (int nb = 0; nb < 4; nb++) {
                    uint32_t vh4[4];
                    uint32_t co = (((uint32_t)(nb*32) + vColS) ^ swf);
                    ldsm4t(vh4, vOff + co);
                    mma16816(o[2*nb],   ph, vh4);
                    mma16816(o[2*nb+1], ph, vh4 + 2);
                    mma16816(o[2*nb],   pl, vh4);
                    mma16816(o[2*nb+1], pl, vh4 + 2);
                }
            }
        }
    }

    {
        float i0 = 1.f / l0, i1 = 1.f / l1;
        __half* base0 = gHs + (size_t)(b*SS + rloc0) * 1024;
        __half* base1 = gHs + (size_t)(b*SS + rloc1) * 1024;
#pragma unroll
        for (int nf = 0; nf < 8; nf++) {
            int col = h*64 + nf*8 + 2*tig;
            uint32_t hi, lo;
            split2(make_float2(o[nf][0]*i0, o[nf][1]*i0), hi, lo);
            *(uint32_t*)&base0[col]       = hi;
            *(uint32_t*)&base0[512 + col] = lo;
            split2(make_float2(o[nf][2]*i1, o[nf][3]*i1), hi, lo);
            *(uint32_t*)&base1[col]       = hi;
            *(uint32_t*)&base1[512 + col] = lo;
        }
    }
#undef LOAD_TILE
}

// ---------------------------------------------------------------------------
extern "C" void kernel_launch(void* const* d_in, const int* in_sizes, int n_in,
                              void* d_out, int out_size)
{
    const float* xs  = (const float*)d_in[0];
    const float* xt  = (const float*)d_in[1];
    const float* Wqs = (const float*)d_in[2];
    const float* Wks = (const float*)d_in[3];
    const float* Wvs = (const float*)d_in[4];
    const float* Wqt = (const float*)d_in[5];
    const float* Wkt = (const float*)d_in[6];
    const float* Wvt = (const float*)d_in[7];
    const float* WKb = (const float*)d_in[8];
    const float* Wo  = (const float*)d_in[9];
    float* out = (float*)d_out;

    const int GEMM_SMEM = 3 * 32768;      // 98304
    const int ATTN_SMEM = 2 * 24576;      // 49152
    cudaFuncSetAttribute(mma_gemm, cudaFuncAttributeMaxDynamicSharedMemorySize, GEMM_SMEM);
    cudaFuncSetAttribute(attn_mma, cudaFuncAttributeMaxDynamicSharedMemorySize, ATTN_SMEM);

    prep_A<<<MROWS, 512>>>(xs, xt);
    prep_W<<<(3*512*2048)/256, 256>>>(Wqs, Wks, Wvs, Wqt, Wkt, Wvt);
    prep_Wo<<<(512*1024)/256, 256>>>(Wo);

    mma_gemm<<<dim3(4, 64, 3), 256, GEMM_SMEM>>>(0, nullptr, WKb);
    attn_mma<<<512, 256, ATTN_SMEM>>>();
    mma_gemm<<<dim3(4, 64, 1), 256, GEMM_SMEM>>>(1, out, WKb);
}